// round 3
// baseline (speedup 1.0000x reference)
#include <cuda_runtime.h>

// ---------------- problem constants ----------------
constexpr int B    = 4;
constexpr int CIN  = 32;
constexpr int NN   = 1024;   // nodes
constexpr int SS   = 32;     // timesteps
constexpr int COUT = 64;
constexpr int CSP  = 64;
constexpr int EE   = 16384;  // edges
constexpr int BN_PART = 64;
constexpr float EPSV = 1e-5f;

// ---------------- device scratch (no allocs allowed) ----------------
__device__ float g_h  [B*NN*COUT*SS];   // conv1 raw  [b][n][c][s]
__device__ float g_hw [B*SS*NN*CSP];    // projection [b][s][n][d]
__device__ float g_agg[B*SS*NN*CSP];    // gcn agg    [b][s][n][d]
__device__ float g_h2 [B*NN*COUT*SS];   // conv2 raw  [b][n][c][s]

__device__ int   g_is64;
__device__ int   g_deg[NN];
__device__ int   g_fill[NN];
__device__ int   g_rowptr[NN+1];
__device__ int   g_col[EE];
__device__ float g_wgt[EE];
__device__ float g_dinv[NN];

__device__ float g_bn1p[2*BN_PART*COUT];
__device__ float g_bn2p[2*BN_PART*COUT];
__device__ float g_bnssum[B*SS*CSP];
__device__ float g_bnssq [B*SS*CSP];
__device__ float g_sc1[COUT], g_sh1[COUT];
__device__ float g_sc2[COUT], g_sh2[COUT];
__device__ float g_scs[B*SS*CSP], g_shs[B*SS*CSP];

// ---------------- dtype detection: int64 edge_index has all-odd-words zero ----------------
__global__ void k_detect(const int* __restrict__ w) {
    // sample 128 odd words spread across first 2*EE words (int32 view of buffer)
    int t = threadIdx.x;                       // 128 threads
    int idx = 2 * (t * 128) + 1;               // odd positions, stride 256 words
    int v = w[idx];
    unsigned any = __ballot_sync(0xffffffffu, v != 0);
    __shared__ int s_any;
    if (t == 0) s_any = 0;
    __syncthreads();
    if ((t & 31) == 0 && any) atomicOr(&s_any, 1);
    __syncthreads();
    if (t == 0) g_is64 = s_any ? 0 : 1;
}

// ---------------- zero transient state ----------------
__global__ void k_zero() {
    int i = blockIdx.x * blockDim.x + threadIdx.x;   // 8192 threads
    if (i < NN) { g_deg[i] = 0; g_fill[i] = 0; }
    if (i < 2*BN_PART*COUT) { g_bn1p[i] = 0.f; g_bn2p[i] = 0.f; }
    if (i < B*SS*CSP) { g_bnssum[i] = 0.f; g_bnssq[i] = 0.f; }
}

// ---------------- degree count ----------------
__global__ void k_deg(const int* __restrict__ w) {
    int e = blockIdx.x * blockDim.x + threadIdx.x;
    if (e >= EE) return;
    int stride = g_is64 ? 2 : 1;
    int d = w[stride * (EE + e)];
    if ((unsigned)d < (unsigned)NN) atomicAdd(&g_deg[d], 1);
}

// ---------------- 1-block scan: rowptr + dinv ----------------
__global__ void k_scan() {
    __shared__ int sh[NN];
    int t = threadIdx.x;
    int c = g_deg[t];
    g_dinv[t] = rsqrtf((float)(c + 1));   // deg includes self loop
    sh[t] = c;
    __syncthreads();
    for (int off = 1; off < NN; off <<= 1) {
        int v = (t >= off) ? sh[t - off] : 0;
        __syncthreads();
        sh[t] += v;
        __syncthreads();
    }
    g_rowptr[t + 1] = sh[t];
    if (t == 0) g_rowptr[0] = 0;
}

// ---------------- CSR fill ----------------
__global__ void k_fill(const int* __restrict__ w) {
    int e = blockIdx.x * blockDim.x + threadIdx.x;
    if (e >= EE) return;
    int stride = g_is64 ? 2 : 1;
    int s = w[stride * e];
    int d = w[stride * (EE + e)];
    if ((unsigned)s >= (unsigned)NN || (unsigned)d >= (unsigned)NN) return;
    int pos = atomicAdd(&g_fill[d], 1);
    int j = g_rowptr[d] + pos;
    g_col[j] = s;
    g_wgt[j] = g_dinv[s] * g_dinv[d];
}

// ---------------- conv1: x[b,cin,n,s] -> g_h[b,n,c,s] raw + BN1 partials ----------------
__global__ void __launch_bounds__(256) k_conv1(const float* __restrict__ x,
                                               const float* __restrict__ W1,
                                               const float* __restrict__ b1) {
    __shared__ float w1s[64 * 97];          // [c][cin*3+k] padded to 97 (24.8KB)
    __shared__ float xs[4 * 32 * 34];       // [node][cin][1+s] (17.4KB)

    int bid = blockIdx.x;
    int b  = bid >> 8;
    int n0 = (bid & 255) * 4;
    int t  = threadIdx.x;

    for (int i = t; i < 64 * 96; i += 256) {
        int c = i / 96, r = i % 96;
        w1s[c * 97 + r] = W1[i];
    }
    for (int i = t; i < 4 * 32; i += 256) { xs[i * 34] = 0.f; xs[i * 34 + 33] = 0.f; }
    for (int i = t; i < 1024; i += 256) {   // 1024 float4
        int nd = i >> 8, cin = (i >> 3) & 31, v = i & 7;
        float4 q = *(const float4*)(x + (((size_t)b * CIN + cin) * NN + (n0 + nd)) * SS + v * 4);
        float* dr = xs + (nd * 32 + cin) * 34 + 1 + v * 4;
        dr[0] = q.x; dr[1] = q.y; dr[2] = q.z; dr[3] = q.w;
    }
    __syncthreads();

    int node = t >> 6, cg = (t >> 2) & 15, sq = t & 3;
    int c0 = cg * 4, s0 = sq * 8;
    float acc[4][8];
#pragma unroll
    for (int a = 0; a < 4; a++)
#pragma unroll
        for (int i = 0; i < 8; i++) acc[a][i] = 0.f;

    const float* xbase = xs + node * 32 * 34;
    for (int cin = 0; cin < CIN; cin++) {
        float xw[10];
        const float* xr = xbase + cin * 34 + s0;   // element s0-1+i
#pragma unroll
        for (int i = 0; i < 10; i++) xw[i] = xr[i];
#pragma unroll
        for (int cc = 0; cc < 4; cc++) {
            const float* wr = w1s + (c0 + cc) * 97 + cin * 3;
            float w0 = wr[0], w1 = wr[1], w2 = wr[2];
#pragma unroll
            for (int i = 0; i < 8; i++)
                acc[cc][i] = fmaf(w0, xw[i], fmaf(w1, xw[i + 1], fmaf(w2, xw[i + 2], acc[cc][i])));
        }
    }

    int n = n0 + node;
    int slot = bid & (BN_PART - 1);
#pragma unroll
    for (int cc = 0; cc < 4; cc++) {
        int c = c0 + cc;
        float bb = b1[c];
        float sm = 0.f, sq2 = 0.f;
        float v[8];
#pragma unroll
        for (int i = 0; i < 8; i++) {
            v[i] = acc[cc][i] + bb;
            sm += v[i]; sq2 += v[i] * v[i];
        }
        float* dst = g_h + (((size_t)b * NN + n) * COUT + c) * SS + s0;
        *(float4*)(dst)     = make_float4(v[0], v[1], v[2], v[3]);
        *(float4*)(dst + 4) = make_float4(v[4], v[5], v[6], v[7]);
        sm  += __shfl_xor_sync(0xffffffffu, sm, 1);  sm  += __shfl_xor_sync(0xffffffffu, sm, 2);
        sq2 += __shfl_xor_sync(0xffffffffu, sq2, 1); sq2 += __shfl_xor_sync(0xffffffffu, sq2, 2);
        if (sq == 0) {
            atomicAdd(&g_bn1p[slot * 64 + c], sm);
            atomicAdd(&g_bn1p[BN_PART * 64 + slot * 64 + c], sq2);
        }
    }
}

// ---------------- BN finalize (channel-wise, which=0 -> bn1, 1 -> bn2) ----------------
__global__ void k_bnfin(const float* __restrict__ g, const float* __restrict__ be,
                        int which, float inv_cnt) {
    int c = threadIdx.x;
    const float* part = (which == 0) ? g_bn1p : g_bn2p;
    float sm = 0.f, sq = 0.f;
    for (int s = 0; s < BN_PART; s++) {
        sm += part[s * 64 + c];
        sq += part[BN_PART * 64 + s * 64 + c];
    }
    float mean = sm * inv_cnt;
    float var  = sq * inv_cnt - mean * mean;
    float sc   = g[c] * rsqrtf(var + EPSV);
    if (which == 0) { g_sc1[c] = sc; g_sh1[c] = be[c] - mean * sc; }
    else            { g_sc2[c] = sc; g_sh2[c] = be[c] - mean * sc; }
}

// ---------------- hw projection: relu(bn1(h)) @ Wg -> g_hw[b,s,n,d]  (2 nodes/block) ----------------
__global__ void __launch_bounds__(256) k_hw(const float* __restrict__ Wg) {
    __shared__ float wgs[64 * 64];      // 16KB  [c][d]
    __shared__ float ht[2 * 64 * 36];   // 18KB  [node][c][s] stride 36

    int bid = blockIdx.x;
    int b  = bid >> 9;
    int n0 = (bid & 511) * 2;
    int t  = threadIdx.x;

    for (int i = t; i < 1024; i += 256)
        *(float4*)(wgs + i * 4) = *(const float4*)(Wg + i * 4);
    for (int i = t; i < 1024; i += 256) {   // 2 nodes * 64c * 32s in float4
        int nd = i >> 9, c = (i >> 3) & 63, v = i & 7;
        float4 q = *(const float4*)(g_h + (((size_t)b * NN + (n0 + nd)) * COUT + c) * SS + v * 4);
        float sc = g_sc1[c], sh = g_sh1[c];
        q.x = fmaxf(fmaf(q.x, sc, sh), 0.f);
        q.y = fmaxf(fmaf(q.y, sc, sh), 0.f);
        q.z = fmaxf(fmaf(q.z, sc, sh), 0.f);
        q.w = fmaxf(fmaf(q.w, sc, sh), 0.f);
        *(float4*)(ht + (nd * 64 + c) * 36 + v * 4) = q;
    }
    __syncthreads();

    int node = t >> 7, tl = t & 127;
    int dg = tl >> 3, sq = tl & 7;
    int d0 = dg * 4, s0 = sq * 4;
    float4 acc4[4];
#pragma unroll
    for (int i = 0; i < 4; i++) acc4[i] = make_float4(0.f, 0.f, 0.f, 0.f);

    for (int c = 0; c < 64; c++) {
        float4 w = *(float4*)(wgs + c * 64 + d0);
        float4 h = *(float4*)(ht + (node * 64 + c) * 36 + s0);
        float hv[4] = {h.x, h.y, h.z, h.w};
#pragma unroll
        for (int i = 0; i < 4; i++) {
            acc4[i].x = fmaf(hv[i], w.x, acc4[i].x);
            acc4[i].y = fmaf(hv[i], w.y, acc4[i].y);
            acc4[i].z = fmaf(hv[i], w.z, acc4[i].z);
            acc4[i].w = fmaf(hv[i], w.w, acc4[i].w);
        }
    }
    int n = n0 + node;
#pragma unroll
    for (int i = 0; i < 4; i++) {
        int s = s0 + i;
        *(float4*)(g_hw + (((size_t)b * SS + s) * NN + n) * CSP + d0) = acc4[i];
    }
}

// ---------------- GCN gather + bg + BN_s partials ----------------
__global__ void __launch_bounds__(256) k_gather(const float* __restrict__ bg) {
    int bid = blockIdx.x;            // 128 * 256
    int bs  = bid >> 8;              // b*S + s
    int n0  = (bid & 255) * 4;
    int t   = threadIdx.x;
    int node = t >> 6, d = t & 63;
    int n = n0 + node;

    const float* hws = g_hw + (size_t)bs * NN * CSP;
    float di = g_dinv[n];
    float acc = hws[n * 64 + d] * di * di;      // self loop
    int jb = g_rowptr[n], je = g_rowptr[n + 1];
    int j = jb;
    for (; j + 4 <= je; j += 4) {
        int c0 = g_col[j], c1 = g_col[j + 1], c2 = g_col[j + 2], c3 = g_col[j + 3];
        float w0 = g_wgt[j], w1 = g_wgt[j + 1], w2 = g_wgt[j + 2], w3 = g_wgt[j + 3];
        float a0 = hws[c0 * 64 + d], a1 = hws[c1 * 64 + d];
        float a2 = hws[c2 * 64 + d], a3 = hws[c3 * 64 + d];
        acc += a0 * w0 + a1 * w1 + a2 * w2 + a3 * w3;
    }
    for (; j < je; j++) acc += hws[g_col[j] * 64 + d] * g_wgt[j];
    acc += bg[d];
    g_agg[((size_t)bs * NN + n) * CSP + d] = acc;

    __shared__ float red[256];
    red[t] = acc;
    __syncthreads();
    float s1 = 0.f;
    if (t < 64) s1 = red[t] + red[t + 64] + red[t + 128] + red[t + 192];
    __syncthreads();
    red[t] = acc * acc;
    __syncthreads();
    if (t < 64) {
        float s2 = red[t] + red[t + 64] + red[t + 128] + red[t + 192];
        atomicAdd(&g_bnssum[bs * 64 + t], s1);
        atomicAdd(&g_bnssq [bs * 64 + t], s2);
    }
}

// ---------------- BN_s finalize ----------------
__global__ void k_bnsfin(const float* __restrict__ gs, const float* __restrict__ bes) {
    int i = blockIdx.x * blockDim.x + threadIdx.x;   // 8192
    if (i >= B * SS * CSP) return;
    int d = i & 63;
    float mean = g_bnssum[i] * (1.f / NN);
    float var  = g_bnssq[i] * (1.f / NN) - mean * mean;
    float sc   = gs[d] * rsqrtf(var + EPSV);
    g_scs[i] = sc;
    g_shs[i] = bes[d] - mean * sc;
}

// ---------------- conv2: relu(bns(agg)) conv W2 -> g_h2 raw  (2 nodes, half channels) -------------
__global__ void __launch_bounds__(256) k_conv2(const float* __restrict__ W2,
                                               const float* __restrict__ b2) {
    __shared__ float w2t[192 * 32];     // [cin*3+k][c_half] 24KB, float4-loadable across c
    __shared__ float s2[2 * 64 * 34];   // [node][d][1+s] 17.4KB

    int bid = blockIdx.x;
    int b    = bid >> 10;
    int r    = bid & 1023;
    int half = r & 1;
    int n0   = (r >> 1) * 2;
    int cb   = half * 32;
    int t    = threadIdx.x;

    for (int i = t; i < 192 * 32; i += 256) {
        int row = i >> 5, cc = i & 31;         // row = cin*3+k
        w2t[i] = W2[(cb + cc) * 192 + row];
    }
    for (int i = t; i < 2 * 64; i += 256) { s2[i * 34] = 0.f; s2[i * 34 + 33] = 0.f; }
    for (int i = t; i < 4096; i += 256) {      // 2n * 32s * 64d scalars
        int d = i & 63, sidx = (i >> 6) & 31, nd = i >> 11;
        int bsi = b * SS + sidx;
        float v = g_agg[((size_t)bsi * NN + (n0 + nd)) * CSP + d];
        v = fmaxf(fmaf(v, g_scs[bsi * 64 + d], g_shs[bsi * 64 + d]), 0.f);
        s2[(nd * 64 + d) * 34 + 1 + sidx] = v;
    }
    __syncthreads();

    int node = t >> 7, tl = t & 127;
    int cg = tl & 7, sg = tl >> 3;
    int c0 = cg * 4, s0 = sg * 2;
    float acc[4][2];
#pragma unroll
    for (int a = 0; a < 4; a++) { acc[a][0] = 0.f; acc[a][1] = 0.f; }

    for (int cin = 0; cin < CSP; cin++) {
        const float* xr = s2 + (node * 64 + cin) * 34 + s0;  // xr[i] = value at s0-1+i
        float x0 = xr[0], x1 = xr[1], x2 = xr[2], x3 = xr[3];
        const float* wb = w2t + cin * 96;
        float4 wk0 = *(float4*)(wb + c0);
        float4 wk1 = *(float4*)(wb + 32 + c0);
        float4 wk2 = *(float4*)(wb + 64 + c0);
        float w0v[4] = {wk0.x, wk0.y, wk0.z, wk0.w};
        float w1v[4] = {wk1.x, wk1.y, wk1.z, wk1.w};
        float w2v[4] = {wk2.x, wk2.y, wk2.z, wk2.w};
#pragma unroll
        for (int cc = 0; cc < 4; cc++) {
            acc[cc][0] = fmaf(w0v[cc], x0, fmaf(w1v[cc], x1, fmaf(w2v[cc], x2, acc[cc][0])));
            acc[cc][1] = fmaf(w0v[cc], x1, fmaf(w1v[cc], x2, fmaf(w2v[cc], x3, acc[cc][1])));
        }
    }

    int n = n0 + node;
#pragma unroll
    for (int cc = 0; cc < 4; cc++) {
        int c = cb + c0 + cc;
        float bb = b2[c];
        float2 v = make_float2(acc[cc][0] + bb, acc[cc][1] + bb);
        *(float2*)(g_h2 + (((size_t)b * NN + n) * COUT + c) * SS + s0) = v;
    }
}

// ---------------- BN2 stats from g_h2 ----------------
__global__ void __launch_bounds__(256) k_stat2() {
    int bid = blockIdx.x;                        // B*NN = 4096 blocks
    int t = threadIdx.x;
    int c = t >> 2, q = t & 3;
    const float4* p = (const float4*)(g_h2 + (size_t)bid * 2048 + c * 32 + q * 8);
    float4 a = p[0], b4 = p[1];
    float sm = a.x + a.y + a.z + a.w + b4.x + b4.y + b4.z + b4.w;
    float sq = a.x*a.x + a.y*a.y + a.z*a.z + a.w*a.w
             + b4.x*b4.x + b4.y*b4.y + b4.z*b4.z + b4.w*b4.w;
    sm += __shfl_xor_sync(0xffffffffu, sm, 1); sm += __shfl_xor_sync(0xffffffffu, sm, 2);
    sq += __shfl_xor_sync(0xffffffffu, sq, 1); sq += __shfl_xor_sync(0xffffffffu, sq, 2);
    if (q == 0) {
        int slot = bid & (BN_PART - 1);
        atomicAdd(&g_bn2p[slot * 64 + c], sm);
        atomicAdd(&g_bn2p[BN_PART * 64 + slot * 64 + c], sq);
    }
}

// ---------------- output: relu( relu(bn2(h2)) + res ) -> out[b,c,n,s] ----------------
__global__ void __launch_bounds__(256) k_out(const float* __restrict__ x,
                                             const float* __restrict__ Wres,
                                             const float* __restrict__ bres,
                                             float* __restrict__ out) {
    __shared__ float wrs[32 * 64];      // [cin][c] 8KB
    __shared__ float xs[4 * 32 * 32];   // [node][cin][s] 16KB

    int bid = blockIdx.x;
    int b  = bid >> 8;
    int n0 = (bid & 255) * 4;
    int t  = threadIdx.x;

    for (int i = t; i < 2048; i += 256) {
        int c = i >> 5, cin = i & 31;
        wrs[cin * 64 + c] = Wres[i];
    }
    for (int i = t; i < 1024; i += 256) {
        int nd = i >> 8, cin = (i >> 3) & 31, v = i & 7;
        float4 q = *(const float4*)(x + (((size_t)b * CIN + cin) * NN + (n0 + nd)) * SS + v * 4);
        *(float4*)(xs + (nd * 32 + cin) * 32 + v * 4) = q;
    }
    __syncthreads();

    int node = t >> 6, cg = (t >> 2) & 15, sq = t & 3;
    int c0 = cg * 4, s0 = sq * 8;
    float acc[4][8];
#pragma unroll
    for (int a = 0; a < 4; a++)
#pragma unroll
        for (int i = 0; i < 8; i++) acc[a][i] = 0.f;

    const float* xbase = xs + node * 32 * 32;
    for (int cin = 0; cin < CIN; cin++) {
        float4 w4 = *(float4*)(wrs + cin * 64 + c0);
        const float* xr = xbase + cin * 32 + s0;
        float4 x0 = *(const float4*)(xr);
        float4 x1 = *(const float4*)(xr + 4);
        float xv[8] = {x0.x, x0.y, x0.z, x0.w, x1.x, x1.y, x1.z, x1.w};
        float wv[4] = {w4.x, w4.y, w4.z, w4.w};
#pragma unroll
        for (int cc = 0; cc < 4; cc++)
#pragma unroll
            for (int i = 0; i < 8; i++)
                acc[cc][i] = fmaf(wv[cc], xv[i], acc[cc][i]);
    }

    int n = n0 + node;
#pragma unroll
    for (int cc = 0; cc < 4; cc++) {
        int c = c0 + cc;
        float sc = g_sc2[c], sh = g_sh2[c], br = bres[c];
        const float4* hp = (const float4*)(g_h2 + (((size_t)b * NN + n) * COUT + c) * SS + s0);
        float4 h0 = hp[0], h1 = hp[1];
        float hraw[8] = {h0.x, h0.y, h0.z, h0.w, h1.x, h1.y, h1.z, h1.w};
        float o[8];
#pragma unroll
        for (int i = 0; i < 8; i++) {
            float hv = fmaxf(fmaf(hraw[i], sc, sh), 0.f);
            o[i] = fmaxf(hv + acc[cc][i] + br, 0.f);
        }
        float* dst = out + (((size_t)b * COUT + c) * NN + n) * SS + s0;
        *(float4*)(dst)     = make_float4(o[0], o[1], o[2], o[3]);
        *(float4*)(dst + 4) = make_float4(o[4], o[5], o[6], o[7]);
    }
}

// ---------------- launch ----------------
extern "C" void kernel_launch(void* const* d_in, const int* in_sizes, int n_in,
                              void* d_out, int out_size) {
    const float* x    = (const float*)d_in[0];
    const int*   eiw  = (const int*)d_in[1];     // int32 view; layout detected on device
    const float* W1   = (const float*)d_in[2];
    const float* b1   = (const float*)d_in[3];
    const float* g1   = (const float*)d_in[4];
    const float* be1  = (const float*)d_in[5];
    const float* Wg   = (const float*)d_in[6];
    const float* bg   = (const float*)d_in[7];
    const float* gs   = (const float*)d_in[8];
    const float* bes  = (const float*)d_in[9];
    const float* W2   = (const float*)d_in[10];
    const float* b2   = (const float*)d_in[11];
    const float* g2   = (const float*)d_in[12];
    const float* be2  = (const float*)d_in[13];
    const float* Wres = (const float*)d_in[14];
    const float* bres = (const float*)d_in[15];
    float*       out  = (float*)d_out;

    k_detect<<<1, 128>>>(eiw);
    k_zero<<<32, 256>>>();
    k_deg <<<EE / 256, 256>>>(eiw);
    k_scan<<<1, NN>>>();
    k_fill<<<EE / 256, 256>>>(eiw);
    k_conv1<<<B * (NN / 4), 256>>>(x, W1, b1);
    k_bnfin<<<1, 64>>>(g1, be1, 0, 1.f / (float)(B * NN * SS));
    k_hw<<<B * (NN / 2), 256>>>(Wg);
    k_gather<<<B * SS * (NN / 4), 256>>>(bg);
    k_bnsfin<<<32, 256>>>(gs, bes);
    k_conv2<<<B * (NN / 2) * 2, 256>>>(W2, b2);
    k_stat2<<<B * NN, 256>>>();
    k_bnfin<<<1, 64>>>(g2, be2, 1, 1.f / (float)(B * NN * SS));
    k_out<<<B * (NN / 4), 256>>>(x, Wres, bres, out);
}

// round 4
// speedup vs baseline: 1.1412x; 1.1412x over previous
#include <cuda_runtime.h>
#include <cuda_fp16.h>

// ---------------- problem constants ----------------
constexpr int B    = 4;
constexpr int CIN  = 32;
constexpr int NN   = 1024;   // nodes
constexpr int SS   = 32;     // timesteps
constexpr int COUT = 64;
constexpr int CSP  = 64;
constexpr int EE   = 16384;  // edges
constexpr int BN_PART = 64;
constexpr float EPSV = 1e-5f;

typedef unsigned long long u64;

// ---------------- packed f32x2 helpers ----------------
__device__ __forceinline__ u64 pack2(float lo, float hi) {
    u64 r;
    asm("mov.b64 %0, {%1, %2};" : "=l"(r) : "f"(lo), "f"(hi));
    return r;
}
__device__ __forceinline__ u64 fma2(u64 a, u64 b, u64 c) {
    u64 d;
    asm("fma.rn.f32x2 %0, %1, %2, %3;" : "=l"(d) : "l"(a), "l"(b), "l"(c));
    return d;
}
__device__ __forceinline__ float2 unpack2(u64 v) {
    float2 f;
    asm("mov.b64 {%0, %1}, %2;" : "=f"(f.x), "=f"(f.y) : "l"(v));
    return f;
}

// ---------------- device scratch ----------------
__device__ float  g_h  [B*NN*COUT*SS];   // conv1 raw  [b][n][c][s]
__device__ __half g_hwh[B*SS*NN*CSP];    // projection [b][s][n][d] fp16
__device__ float  g_agg[B*SS*NN*CSP];    // gcn agg    [b][s][n][d]
__device__ float  g_h2 [B*NN*COUT*SS];   // conv2 raw  [b][n][c][s]

__device__ float  g_W1t[96*64];          // W1 transposed [cin*3+k][c]
__device__ float  g_W2t[192*64];         // W2 transposed [cin*3+k][c]

__device__ int   g_is64;
__device__ int   g_deg[NN];
__device__ int   g_fill[NN];
__device__ int   g_rowptr[NN+1];
__device__ int   g_col[EE];
__device__ float g_wgt[EE];
__device__ float g_dinv[NN];

__device__ float g_bn1p[2*BN_PART*COUT];
__device__ float g_bn2p[2*BN_PART*COUT];
__device__ float g_bnssum[B*SS*CSP];
__device__ float g_bnssq [B*SS*CSP];
__device__ float g_sc1[COUT], g_sh1[COUT];
__device__ float g_sc2[COUT], g_sh2[COUT];
__device__ float g_scs[B*SS*CSP], g_shs[B*SS*CSP];

// ---------------- dtype detection ----------------
__global__ void k_detect(const int* __restrict__ w) {
    int t = threadIdx.x;                       // 128 threads
    int idx = 2 * (t * 128) + 1;
    int v = w[idx];
    unsigned any = __ballot_sync(0xffffffffu, v != 0);
    __shared__ int s_any;
    if (t == 0) s_any = 0;
    __syncthreads();
    if ((t & 31) == 0 && any) atomicOr(&s_any, 1);
    __syncthreads();
    if (t == 0) g_is64 = s_any ? 0 : 1;
}

// ---------------- zero transient state ----------------
__global__ void k_zero() {
    int i = blockIdx.x * blockDim.x + threadIdx.x;
    if (i < NN) { g_deg[i] = 0; g_fill[i] = 0; }
    if (i < 2*BN_PART*COUT) { g_bn1p[i] = 0.f; g_bn2p[i] = 0.f; }
    if (i < B*SS*CSP) { g_bnssum[i] = 0.f; g_bnssq[i] = 0.f; }
}

// ---------------- weight transpose (once per call, tiny) ----------------
__global__ void k_wt(const float* __restrict__ W1, const float* __restrict__ W2) {
    int i = blockIdx.x * 256 + threadIdx.x;   // 12288 threads
    if (i < 96*64)  g_W1t[i] = W1[(i & 63) * 96  + (i >> 6)];
    if (i < 192*64) g_W2t[i] = W2[(i & 63) * 192 + (i >> 6)];
}

// ---------------- degree count ----------------
__global__ void k_deg(const int* __restrict__ w) {
    int e = blockIdx.x * blockDim.x + threadIdx.x;
    if (e >= EE) return;
    int stride = g_is64 ? 2 : 1;
    int d = w[stride * (EE + e)];
    if ((unsigned)d < (unsigned)NN) atomicAdd(&g_deg[d], 1);
}

// ---------------- 1-block scan ----------------
__global__ void k_scan() {
    __shared__ int sh[NN];
    int t = threadIdx.x;
    int c = g_deg[t];
    g_dinv[t] = rsqrtf((float)(c + 1));
    sh[t] = c;
    __syncthreads();
    for (int off = 1; off < NN; off <<= 1) {
        int v = (t >= off) ? sh[t - off] : 0;
        __syncthreads();
        sh[t] += v;
        __syncthreads();
    }
    g_rowptr[t + 1] = sh[t];
    if (t == 0) g_rowptr[0] = 0;
}

// ---------------- CSR fill ----------------
__global__ void k_fill(const int* __restrict__ w) {
    int e = blockIdx.x * blockDim.x + threadIdx.x;
    if (e >= EE) return;
    int stride = g_is64 ? 2 : 1;
    int s = w[stride * e];
    int d = w[stride * (EE + e)];
    if ((unsigned)s >= (unsigned)NN || (unsigned)d >= (unsigned)NN) return;
    int pos = atomicAdd(&g_fill[d], 1);
    int j = g_rowptr[d] + pos;
    g_col[j] = s;
    g_wgt[j] = g_dinv[s] * g_dinv[d];
}

// ---------------- conv1 (FFMA2, 8c x 4s per thread): x -> g_h raw + BN1 partials -----------
__global__ void __launch_bounds__(256) k_conv1(const float* __restrict__ x,
                                               const float* __restrict__ b1) {
    __shared__ float w1s[96 * 64];          // [row][c] 24KB
    __shared__ float xs[4 * 32 * 34];       // [node][cin][1+s] 17.4KB

    int bid = blockIdx.x;
    int b  = bid >> 8;
    int n0 = (bid & 255) * 4;
    int t  = threadIdx.x;

    for (int i = t; i < 96 * 16; i += 256)
        *(float4*)(w1s + i * 4) = *(const float4*)(g_W1t + i * 4);
    for (int i = t; i < 4 * 32; i += 256) { xs[i * 34] = 0.f; xs[i * 34 + 33] = 0.f; }
    for (int i = t; i < 1024; i += 256) {
        int nd = i >> 8, cin = (i >> 3) & 31, v = i & 7;
        float4 q = *(const float4*)(x + (((size_t)b * CIN + cin) * NN + (n0 + nd)) * SS + v * 4);
        float* dr = xs + (nd * 32 + cin) * 34 + 1 + v * 4;
        dr[0] = q.x; dr[1] = q.y; dr[2] = q.z; dr[3] = q.w;
    }
    __syncthreads();

    int node = t >> 6, tl = t & 63;
    int cg = tl >> 3, sg = tl & 7;
    int c0 = cg * 8, s0 = sg * 4;

    u64 acc2[4][4];
#pragma unroll
    for (int p = 0; p < 4; p++)
#pragma unroll
        for (int i = 0; i < 4; i++) acc2[p][i] = 0ull;

    for (int cin = 0; cin < CIN; cin++) {
        const float* xr = xs + (node * 32 + cin) * 34 + s0;  // xr[j] = x at s0-1+j
        u64 xb[6];
#pragma unroll
        for (int j = 0; j < 6; j++) { float v = xr[j]; xb[j] = pack2(v, v); }
        const float* wr = w1s + cin * 3 * 64 + c0;
#pragma unroll
        for (int k = 0; k < 3; k++) {
            u64 w0 = *(const u64*)(wr + k * 64);
            u64 w1 = *(const u64*)(wr + k * 64 + 2);
            u64 w2 = *(const u64*)(wr + k * 64 + 4);
            u64 w3 = *(const u64*)(wr + k * 64 + 6);
#pragma unroll
            for (int i = 0; i < 4; i++) {
                acc2[0][i] = fma2(w0, xb[i + k], acc2[0][i]);
                acc2[1][i] = fma2(w1, xb[i + k], acc2[1][i]);
                acc2[2][i] = fma2(w2, xb[i + k], acc2[2][i]);
                acc2[3][i] = fma2(w3, xb[i + k], acc2[3][i]);
            }
        }
    }

    float vch[8][4];
#pragma unroll
    for (int p = 0; p < 4; p++)
#pragma unroll
        for (int i = 0; i < 4; i++) {
            float2 f = unpack2(acc2[p][i]);
            vch[2 * p][i] = f.x; vch[2 * p + 1][i] = f.y;
        }

    int n = n0 + node;
    int slot = bid & (BN_PART - 1);
#pragma unroll
    for (int cc = 0; cc < 8; cc++) {
        int c = c0 + cc;
        float bb = b1[c];
        float v0 = vch[cc][0] + bb, v1 = vch[cc][1] + bb;
        float v2 = vch[cc][2] + bb, v3 = vch[cc][3] + bb;
        *(float4*)(g_h + (((size_t)b * NN + n) * COUT + c) * SS + s0) =
            make_float4(v0, v1, v2, v3);
        float sm = v0 + v1 + v2 + v3;
        float sq = v0*v0 + v1*v1 + v2*v2 + v3*v3;
        sm += __shfl_xor_sync(0xffffffffu, sm, 1);
        sm += __shfl_xor_sync(0xffffffffu, sm, 2);
        sm += __shfl_xor_sync(0xffffffffu, sm, 4);
        sq += __shfl_xor_sync(0xffffffffu, sq, 1);
        sq += __shfl_xor_sync(0xffffffffu, sq, 2);
        sq += __shfl_xor_sync(0xffffffffu, sq, 4);
        if (sg == 0) {
            atomicAdd(&g_bn1p[slot * 64 + c], sm);
            atomicAdd(&g_bn1p[BN_PART * 64 + slot * 64 + c], sq);
        }
    }
}

// ---------------- BN finalize ----------------
__global__ void k_bnfin(const float* __restrict__ g, const float* __restrict__ be,
                        int which, float inv_cnt) {
    int c = threadIdx.x;
    const float* part = (which == 0) ? g_bn1p : g_bn2p;
    float sm = 0.f, sq = 0.f;
    for (int s = 0; s < BN_PART; s++) {
        sm += part[s * 64 + c];
        sq += part[BN_PART * 64 + s * 64 + c];
    }
    float mean = sm * inv_cnt;
    float var  = sq * inv_cnt - mean * mean;
    float sc   = g[c] * rsqrtf(var + EPSV);
    if (which == 0) { g_sc1[c] = sc; g_sh1[c] = be[c] - mean * sc; }
    else            { g_sc2[c] = sc; g_sh2[c] = be[c] - mean * sc; }
}

// ---------------- hw projection (FFMA2): relu(bn1(h)) @ Wg -> g_hwh fp16 ----------------
__global__ void __launch_bounds__(256) k_hw(const float* __restrict__ Wg) {
    __shared__ float wgs[64 * 64];      // 16KB  [c][d]
    __shared__ float ht[2 * 64 * 36];   // 18KB  [node][c][s] stride 36

    int bid = blockIdx.x;
    int b  = bid >> 9;
    int n0 = (bid & 511) * 2;
    int t  = threadIdx.x;

    for (int i = t; i < 1024; i += 256)
        *(float4*)(wgs + i * 4) = *(const float4*)(Wg + i * 4);
    for (int i = t; i < 1024; i += 256) {
        int nd = i >> 9, c = (i >> 3) & 63, v = i & 7;
        float4 q = *(const float4*)(g_h + (((size_t)b * NN + (n0 + nd)) * COUT + c) * SS + v * 4);
        float sc = g_sc1[c], sh = g_sh1[c];
        q.x = fmaxf(fmaf(q.x, sc, sh), 0.f);
        q.y = fmaxf(fmaf(q.y, sc, sh), 0.f);
        q.z = fmaxf(fmaf(q.z, sc, sh), 0.f);
        q.w = fmaxf(fmaf(q.w, sc, sh), 0.f);
        *(float4*)(ht + (nd * 64 + c) * 36 + v * 4) = q;
    }
    __syncthreads();

    int node = t >> 7, tl = t & 127;
    int dg = tl >> 3, sq = tl & 7;
    int d0 = dg * 4, s0 = sq * 4;
    u64 acc01[4], acc23[4];
#pragma unroll
    for (int i = 0; i < 4; i++) { acc01[i] = 0ull; acc23[i] = 0ull; }

    for (int c = 0; c < 64; c++) {
        u64 w01 = *(const u64*)(wgs + c * 64 + d0);
        u64 w23 = *(const u64*)(wgs + c * 64 + d0 + 2);
        float4 h = *(float4*)(ht + (node * 64 + c) * 36 + s0);
        u64 hb[4] = { pack2(h.x, h.x), pack2(h.y, h.y), pack2(h.z, h.z), pack2(h.w, h.w) };
#pragma unroll
        for (int i = 0; i < 4; i++) {
            acc01[i] = fma2(w01, hb[i], acc01[i]);
            acc23[i] = fma2(w23, hb[i], acc23[i]);
        }
    }
    int n = n0 + node;
#pragma unroll
    for (int i = 0; i < 4; i++) {
        int s = s0 + i;
        float2 f01 = unpack2(acc01[i]);
        float2 f23 = unpack2(acc23[i]);
        __half2 a = __floats2half2_rn(f01.x, f01.y);
        __half2 c2 = __floats2half2_rn(f23.x, f23.y);
        uint2 u;
        u.x = *(unsigned*)&a; u.y = *(unsigned*)&c2;
        *(uint2*)(g_hwh + (((size_t)b * SS + s) * NN + n) * CSP + d0) = u;
    }
}

// ---------------- GCN gather (half2 reads) + bg + BN_s partials ----------------
__global__ void __launch_bounds__(256) k_gather(const float* __restrict__ bg) {
    int bid = blockIdx.x;            // 128 bs * 128 nodegroups
    int bs  = bid >> 7;
    int n0  = (bid & 127) * 8;
    int t   = threadIdx.x;
    int wr  = t >> 5, lane = t & 31;
    int n = n0 + wr, d = lane * 2;

    const __half* hws = g_hwh + (size_t)bs * NN * CSP;
    float di = g_dinv[n];
    float sl = di * di;
    float2 f0 = __half22float2(*(const __half2*)(hws + n * 64 + d));
    float ax = f0.x * sl, ay = f0.y * sl;

    int jb = g_rowptr[n], je = g_rowptr[n + 1];
    int j = jb;
    for (; j + 4 <= je; j += 4) {
        int c0 = g_col[j], c1 = g_col[j+1], c2 = g_col[j+2], c3 = g_col[j+3];
        float w0 = g_wgt[j], w1 = g_wgt[j+1], w2 = g_wgt[j+2], w3 = g_wgt[j+3];
        float2 a0 = __half22float2(*(const __half2*)(hws + c0 * 64 + d));
        float2 a1 = __half22float2(*(const __half2*)(hws + c1 * 64 + d));
        float2 a2 = __half22float2(*(const __half2*)(hws + c2 * 64 + d));
        float2 a3 = __half22float2(*(const __half2*)(hws + c3 * 64 + d));
        ax += a0.x*w0 + a1.x*w1 + a2.x*w2 + a3.x*w3;
        ay += a0.y*w0 + a1.y*w1 + a2.y*w2 + a3.y*w3;
    }
    for (; j < je; j++) {
        float w = g_wgt[j];
        float2 a = __half22float2(*(const __half2*)(hws + g_col[j] * 64 + d));
        ax += a.x * w; ay += a.y * w;
    }
    ax += bg[d]; ay += bg[d + 1];
    *(float2*)(g_agg + ((size_t)bs * NN + n) * CSP + d) = make_float2(ax, ay);

    __shared__ float red[8 * 64];
    red[wr * 64 + d] = ax; red[wr * 64 + d + 1] = ay;
    __syncthreads();
    if (t < 64) {
        float s1 = 0.f;
#pragma unroll
        for (int r = 0; r < 8; r++) s1 += red[r * 64 + t];
        atomicAdd(&g_bnssum[bs * 64 + t], s1);
    }
    __syncthreads();
    red[wr * 64 + d] = ax * ax; red[wr * 64 + d + 1] = ay * ay;
    __syncthreads();
    if (t < 64) {
        float s2 = 0.f;
#pragma unroll
        for (int r = 0; r < 8; r++) s2 += red[r * 64 + t];
        atomicAdd(&g_bnssq[bs * 64 + t], s2);
    }
}

// ---------------- BN_s finalize ----------------
__global__ void k_bnsfin(const float* __restrict__ gs, const float* __restrict__ bes) {
    int i = blockIdx.x * blockDim.x + threadIdx.x;
    if (i >= B * SS * CSP) return;
    int d = i & 63;
    float mean = g_bnssum[i] * (1.f / NN);
    float var  = g_bnssq[i] * (1.f / NN) - mean * mean;
    float sc   = gs[d] * rsqrtf(var + EPSV);
    g_scs[i] = sc;
    g_shs[i] = bes[d] - mean * sc;
}

// ---------------- conv2 (FFMA2, 8c x 4s, full channels, 4 nodes): + BN2 partials ----------
__global__ void __launch_bounds__(256) k_conv2(const float* __restrict__ b2) {
    extern __shared__ float dsm[];
    float* w2s = dsm;                  // [row][c] 192*64 = 48KB
    float* s2  = dsm + 192 * 64;       // [node][d][1+s] 4*64*34 = 34KB

    int bid = blockIdx.x;
    int b  = bid >> 8;
    int n0 = (bid & 255) * 4;
    int t  = threadIdx.x;

    for (int i = t; i < 192 * 16; i += 256)
        *(float4*)(w2s + i * 4) = *(const float4*)(g_W2t + i * 4);
    for (int i = t; i < 4 * 64; i += 256) { s2[i * 34] = 0.f; s2[i * 34 + 33] = 0.f; }
    for (int i = t; i < 8192; i += 256) {
        int d = i & 63, sidx = (i >> 6) & 31, nd = i >> 11;
        int bsi = b * SS + sidx;
        float v = g_agg[((size_t)bsi * NN + (n0 + nd)) * CSP + d];
        v = fmaxf(fmaf(v, g_scs[bsi * 64 + d], g_shs[bsi * 64 + d]), 0.f);
        s2[(nd * 64 + d) * 34 + 1 + sidx] = v;
    }
    __syncthreads();

    int node = t >> 6, tl = t & 63;
    int cg = tl >> 3, sg = tl & 7;
    int c0 = cg * 8, s0 = sg * 4;

    u64 acc2[4][4];
#pragma unroll
    for (int p = 0; p < 4; p++)
#pragma unroll
        for (int i = 0; i < 4; i++) acc2[p][i] = 0ull;

    for (int cin = 0; cin < CSP; cin++) {
        const float* xr = s2 + (node * 64 + cin) * 34 + s0;
        u64 xb[6];
#pragma unroll
        for (int j = 0; j < 6; j++) { float v = xr[j]; xb[j] = pack2(v, v); }
        const float* wrp = w2s + cin * 3 * 64 + c0;
#pragma unroll
        for (int k = 0; k < 3; k++) {
            u64 w0 = *(const u64*)(wrp + k * 64);
            u64 w1 = *(const u64*)(wrp + k * 64 + 2);
            u64 w2 = *(const u64*)(wrp + k * 64 + 4);
            u64 w3 = *(const u64*)(wrp + k * 64 + 6);
#pragma unroll
            for (int i = 0; i < 4; i++) {
                acc2[0][i] = fma2(w0, xb[i + k], acc2[0][i]);
                acc2[1][i] = fma2(w1, xb[i + k], acc2[1][i]);
                acc2[2][i] = fma2(w2, xb[i + k], acc2[2][i]);
                acc2[3][i] = fma2(w3, xb[i + k], acc2[3][i]);
            }
        }
    }

    float vch[8][4];
#pragma unroll
    for (int p = 0; p < 4; p++)
#pragma unroll
        for (int i = 0; i < 4; i++) {
            float2 f = unpack2(acc2[p][i]);
            vch[2 * p][i] = f.x; vch[2 * p + 1][i] = f.y;
        }

    int n = n0 + node;
    int slot = bid & (BN_PART - 1);
#pragma unroll
    for (int cc = 0; cc < 8; cc++) {
        int c = c0 + cc;
        float bb = b2[c];
        float v0 = vch[cc][0] + bb, v1 = vch[cc][1] + bb;
        float v2 = vch[cc][2] + bb, v3 = vch[cc][3] + bb;
        *(float4*)(g_h2 + (((size_t)b * NN + n) * COUT + c) * SS + s0) =
            make_float4(v0, v1, v2, v3);
        float sm = v0 + v1 + v2 + v3;
        float sq = v0*v0 + v1*v1 + v2*v2 + v3*v3;
        sm += __shfl_xor_sync(0xffffffffu, sm, 1);
        sm += __shfl_xor_sync(0xffffffffu, sm, 2);
        sm += __shfl_xor_sync(0xffffffffu, sm, 4);
        sq += __shfl_xor_sync(0xffffffffu, sq, 1);
        sq += __shfl_xor_sync(0xffffffffu, sq, 2);
        sq += __shfl_xor_sync(0xffffffffu, sq, 4);
        if (sg == 0) {
            atomicAdd(&g_bn2p[slot * 64 + c], sm);
            atomicAdd(&g_bn2p[BN_PART * 64 + slot * 64 + c], sq);
        }
    }
}

// ---------------- output: relu( relu(bn2(h2)) + res ) -> out[b,c,n,s] ----------------
__global__ void __launch_bounds__(256) k_out(const float* __restrict__ x,
                                             const float* __restrict__ Wres,
                                             const float* __restrict__ bres,
                                             float* __restrict__ out) {
    __shared__ float wrs[32 * 64];      // [cin][c]
    __shared__ float xs[4 * 32 * 32];   // [node][cin][s]

    int bid = blockIdx.x;
    int b  = bid >> 8;
    int n0 = (bid & 255) * 4;
    int t  = threadIdx.x;

    for (int i = t; i < 2048; i += 256) {
        int c = i >> 5, cin = i & 31;
        wrs[cin * 64 + c] = Wres[i];
    }
    for (int i = t; i < 1024; i += 256) {
        int nd = i >> 8, cin = (i >> 3) & 31, v = i & 7;
        float4 q = *(const float4*)(x + (((size_t)b * CIN + cin) * NN + (n0 + nd)) * SS + v * 4);
        *(float4*)(xs + (nd * 32 + cin) * 32 + v * 4) = q;
    }
    __syncthreads();

    int node = t >> 6, cg = (t >> 2) & 15, sq = t & 3;
    int c0 = cg * 4, s0 = sq * 8;
    float acc[4][8];
#pragma unroll
    for (int a = 0; a < 4; a++)
#pragma unroll
        for (int i = 0; i < 8; i++) acc[a][i] = 0.f;

    const float* xbase = xs + node * 32 * 32;
    for (int cin = 0; cin < CIN; cin++) {
        float4 w4 = *(float4*)(wrs + cin * 64 + c0);
        const float* xr = xbase + cin * 32 + s0;
        float4 x0 = *(const float4*)(xr);
        float4 x1 = *(const float4*)(xr + 4);
        float xv[8] = {x0.x, x0.y, x0.z, x0.w, x1.x, x1.y, x1.z, x1.w};
        float wv[4] = {w4.x, w4.y, w4.z, w4.w};
#pragma unroll
        for (int cc = 0; cc < 4; cc++)
#pragma unroll
            for (int i = 0; i < 8; i++)
                acc[cc][i] = fmaf(wv[cc], xv[i], acc[cc][i]);
    }

    int n = n0 + node;
#pragma unroll
    for (int cc = 0; cc < 4; cc++) {
        int c = c0 + cc;
        float sc = g_sc2[c], sh = g_sh2[c], br = bres[c];
        const float4* hp = (const float4*)(g_h2 + (((size_t)b * NN + n) * COUT + c) * SS + s0);
        float4 h0 = hp[0], h1 = hp[1];
        float hraw[8] = {h0.x, h0.y, h0.z, h0.w, h1.x, h1.y, h1.z, h1.w};
        float o[8];
#pragma unroll
        for (int i = 0; i < 8; i++) {
            float hv = fmaxf(fmaf(hraw[i], sc, sh), 0.f);
            o[i] = fmaxf(hv + acc[cc][i] + br, 0.f);
        }
        float* dst = out + (((size_t)b * COUT + c) * NN + n) * SS + s0;
        *(float4*)(dst)     = make_float4(o[0], o[1], o[2], o[3]);
        *(float4*)(dst + 4) = make_float4(o[4], o[5], o[6], o[7]);
    }
}

// ---------------- launch ----------------
extern "C" void kernel_launch(void* const* d_in, const int* in_sizes, int n_in,
                              void* d_out, int out_size) {
    const float* x    = (const float*)d_in[0];
    const int*   eiw  = (const int*)d_in[1];
    const float* W1   = (const float*)d_in[2];
    const float* b1   = (const float*)d_in[3];
    const float* g1   = (const float*)d_in[4];
    const float* be1  = (const float*)d_in[5];
    const float* Wg   = (const float*)d_in[6];
    const float* bg   = (const float*)d_in[7];
    const float* gs   = (const float*)d_in[8];
    const float* bes  = (const float*)d_in[9];
    const float* W2   = (const float*)d_in[10];
    const float* b2   = (const float*)d_in[11];
    const float* g2   = (const float*)d_in[12];
    const float* be2  = (const float*)d_in[13];
    const float* Wres = (const float*)d_in[14];
    const float* bres = (const float*)d_in[15];
    float*       out  = (float*)d_out;

    const int SMEM_C2 = (192 * 64 + 4 * 64 * 34) * 4;   // 83968 bytes
    cudaFuncSetAttribute(k_conv2, cudaFuncAttributeMaxDynamicSharedMemorySize, SMEM_C2);

    k_detect<<<1, 128>>>(eiw);
    k_zero<<<32, 256>>>();
    k_wt<<<48, 256>>>(W1, W2);
    k_deg <<<EE / 256, 256>>>(eiw);
    k_scan<<<1, NN>>>();
    k_fill<<<EE / 256, 256>>>(eiw);
    k_conv1<<<B * (NN / 4), 256>>>(x, b1);
    k_bnfin<<<1, 64>>>(g1, be1, 0, 1.f / (float)(B * NN * SS));
    k_hw<<<B * (NN / 2), 256>>>(Wg);
    k_gather<<<B * SS * (NN / 8), 256>>>(bg);
    k_bnsfin<<<32, 256>>>(gs, bes);
    k_conv2<<<B * (NN / 4), 256, SMEM_C2>>>(b2);
    k_bnfin<<<1, 64>>>(g2, be2, 1, 1.f / (float)(B * NN * SS));
    k_out<<<B * (NN / 4), 256>>>(x, Wres, bres, out);
}

// round 5
// speedup vs baseline: 2.1225x; 1.8599x over previous
#include <cuda_runtime.h>
#include <cuda_fp16.h>

// ---------------- problem constants ----------------
constexpr int B    = 4;
constexpr int CIN  = 32;
constexpr int NN   = 1024;   // nodes
constexpr int SS   = 32;     // timesteps
constexpr int COUT = 64;
constexpr int CSP  = 64;
constexpr int EE   = 16384;  // edges
constexpr int BN_PART = 64;
constexpr float EPSV = 1e-5f;

// ---------------- device scratch ----------------
__device__ float  g_ht [B*NN*SS*COUT];   // conv1 raw TRANSPOSED [b][n][s][c]
__device__ __half g_hwh[B*SS*NN*CSP];    // projection [b][s][n][d] fp16
__device__ float  g_agg[B*SS*NN*CSP];    // gcn agg    [b][s][n][d]
__device__ float  g_h2t[B*NN*SS*COUT];   // conv2 raw TRANSPOSED [b][n][s][c]

__device__ __half g_W1h[64*96];          // W1 fp16 [c][cin*3]
__device__ __half g_W2h[64*192];         // W2 fp16 [c][cin*3]
__device__ __half g_Wgh[64*64];          // Wg^T fp16 [d][c]

__device__ int   g_is64;
__device__ int   g_deg[NN];
__device__ int   g_fill[NN];
__device__ int   g_rowptr[NN+1];
__device__ int   g_col[EE];
__device__ float g_wgt[EE];
__device__ float g_dinv[NN];

__device__ float g_bn1p[2*BN_PART*COUT];
__device__ float g_bn2p[2*BN_PART*COUT];
__device__ float g_bnssum[B*SS*CSP];
__device__ float g_bnssq [B*SS*CSP];
__device__ float g_sc1[COUT], g_sh1[COUT];
__device__ float g_sc2[COUT], g_sh2[COUT];
__device__ float g_scs[B*SS*CSP], g_shs[B*SS*CSP];

// ---------------- mma helpers ----------------
__device__ __forceinline__ unsigned su32(const void* p) {
    return (unsigned)__cvta_generic_to_shared(p);
}
__device__ __forceinline__ void ldmA(unsigned addr, unsigned& a0, unsigned& a1,
                                     unsigned& a2, unsigned& a3) {
    asm volatile("ldmatrix.sync.aligned.m8n8.x4.shared.b16 {%0,%1,%2,%3}, [%4];"
                 : "=r"(a0), "=r"(a1), "=r"(a2), "=r"(a3) : "r"(addr));
}
__device__ __forceinline__ void ldmB(unsigned addr, unsigned& b0, unsigned& b1) {
    asm volatile("ldmatrix.sync.aligned.m8n8.x2.shared.b16 {%0,%1}, [%2];"
                 : "=r"(b0), "=r"(b1) : "r"(addr));
}
__device__ __forceinline__ void mma16816(float* c, unsigned a0, unsigned a1,
                                         unsigned a2, unsigned a3,
                                         unsigned b0, unsigned b1) {
    asm volatile("mma.sync.aligned.m16n8k16.row.col.f32.f16.f16.f32 "
                 "{%0,%1,%2,%3},{%4,%5,%6,%7},{%8,%9},{%0,%1,%2,%3};"
                 : "+f"(c[0]), "+f"(c[1]), "+f"(c[2]), "+f"(c[3])
                 : "r"(a0), "r"(a1), "r"(a2), "r"(a3), "r"(b0), "r"(b1));
}

// ---------------- dtype detection ----------------
__global__ void k_detect(const int* __restrict__ w) {
    int t = threadIdx.x;
    int v = w[2 * (t * 128) + 1];
    unsigned any = __ballot_sync(0xffffffffu, v != 0);
    __shared__ int s_any;
    if (t == 0) s_any = 0;
    __syncthreads();
    if ((t & 31) == 0 && any) atomicOr(&s_any, 1);
    __syncthreads();
    if (t == 0) g_is64 = s_any ? 0 : 1;
}

// ---------------- zero transient state ----------------
__global__ void k_zero() {
    int i = blockIdx.x * blockDim.x + threadIdx.x;
    if (i < NN) { g_deg[i] = 0; g_fill[i] = 0; }
    if (i < 2*BN_PART*COUT) { g_bn1p[i] = 0.f; g_bn2p[i] = 0.f; }
    if (i < B*SS*CSP) { g_bnssum[i] = 0.f; g_bnssq[i] = 0.f; }
}

// ---------------- weight convert (fp32 -> fp16) ----------------
__global__ void k_wt(const float* __restrict__ W1, const float* __restrict__ W2,
                     const float* __restrict__ Wg) {
    int i = blockIdx.x * 256 + threadIdx.x;   // 12288 threads
    if (i < 64*96)  g_W1h[i] = __float2half(W1[i]);
    if (i < 64*192) g_W2h[i] = __float2half(W2[i]);
    if (i < 64*64)  g_Wgh[i] = __float2half(Wg[(i & 63) * 64 + (i >> 6)]);  // [d][c]
}

// ---------------- degree count ----------------
__global__ void k_deg(const int* __restrict__ w) {
    int e = blockIdx.x * blockDim.x + threadIdx.x;
    if (e >= EE) return;
    int stride = g_is64 ? 2 : 1;
    int d = w[stride * (EE + e)];
    if ((unsigned)d < (unsigned)NN) atomicAdd(&g_deg[d], 1);
}

// ---------------- 1-block scan ----------------
__global__ void k_scan() {
    __shared__ int sh[NN];
    int t = threadIdx.x;
    int c = g_deg[t];
    g_dinv[t] = rsqrtf((float)(c + 1));
    sh[t] = c;
    __syncthreads();
    for (int off = 1; off < NN; off <<= 1) {
        int v = (t >= off) ? sh[t - off] : 0;
        __syncthreads();
        sh[t] += v;
        __syncthreads();
    }
    g_rowptr[t + 1] = sh[t];
    if (t == 0) g_rowptr[0] = 0;
}

// ---------------- CSR fill ----------------
__global__ void k_fill(const int* __restrict__ w) {
    int e = blockIdx.x * blockDim.x + threadIdx.x;
    if (e >= EE) return;
    int stride = g_is64 ? 2 : 1;
    int s = w[stride * e];
    int d = w[stride * (EE + e)];
    if ((unsigned)s >= (unsigned)NN || (unsigned)d >= (unsigned)NN) return;
    int pos = atomicAdd(&g_fill[d], 1);
    int j = g_rowptr[d] + pos;
    g_col[j] = s;
    g_wgt[j] = g_dinv[s] * g_dinv[d];
}

// ================= tensor-core conv (shared machinery) =================
// MMA core: M=128 pos (4 nodes x 32 s), N=64 ch, K templated. A/B fp16 smem, C fp32.
template<int K>
__device__ __forceinline__ void conv_mma_core(const __half* As, const __half* Bs,
                                              float* Cs, int t) {
    constexpr int LD = K + 8;   // half stride
    int wm = t >> 5, lane = t & 31;
    float acc[8][4];
#pragma unroll
    for (int nt = 0; nt < 8; nt++)
#pragma unroll
        for (int i = 0; i < 4; i++) acc[nt][i] = 0.f;

    unsigned aBase = su32(As) + ((wm * 16 + (lane & 15)) * LD + (lane >> 4) * 8) * 2;
    unsigned bBase = su32(Bs) + ((lane & 7) * LD + ((lane >> 3) & 1) * 8) * 2;

#pragma unroll
    for (int kb = 0; kb < K / 16; kb++) {
        unsigned a0, a1, a2, a3;
        ldmA(aBase + kb * 32, a0, a1, a2, a3);
#pragma unroll
        for (int nt = 0; nt < 8; nt++) {
            unsigned b0, b1;
            ldmB(bBase + (unsigned)(nt * 8 * LD) * 2 + kb * 32, b0, b1);
            mma16816(acc[nt], a0, a1, a2, a3, b0, b1);
        }
    }
    __syncthreads();   // As dead; Cs may alias As
#pragma unroll
    for (int nt = 0; nt < 8; nt++) {
        int r0 = wm * 16 + (lane >> 2);
        int col = nt * 8 + (lane & 3) * 2;
        *(float2*)&Cs[r0 * 68 + col]       = make_float2(acc[nt][0], acc[nt][1]);
        *(float2*)&Cs[(r0 + 8) * 68 + col] = make_float2(acc[nt][2], acc[nt][3]);
    }
    __syncthreads();
}

// im2col: As[pos][cin*3+tap] = Xs[nd][cin][ (pos&31) + tap ]  (halo layout, 34 wide)
template<int K, int CIN_T>
__device__ __forceinline__ void im2col(const __half* Xs, __half* As, int t) {
    constexpr int LD = K + 8;
    int pos = t >> 1, kh = t & 1;
    int nd = pos >> 5, s = pos & 31;
    const __half* xrow = Xs + (nd * CIN_T) * 34 + s;
    __half* arow = As + pos * LD;
#pragma unroll
    for (int cin = kh * (CIN_T / 2); cin < (kh + 1) * (CIN_T / 2); cin++) {
        const __half* xr = xrow + cin * 34;
        arow[cin * 3 + 0] = xr[0];
        arow[cin * 3 + 1] = xr[1];
        arow[cin * 3 + 2] = xr[2];
    }
}

// epilogue: Cs[pos][c]+bias -> gdst (linear [pos*64+c]), BN partials to part[]
__device__ __forceinline__ void conv_epi(const float* Cs, float* gdst,
                                         const float* __restrict__ bias,
                                         float* part, int slot, int t) {
    int c = t & 63, ndt = t >> 6;
    float bb = bias[c];
    float sm = 0.f, sq = 0.f;
#pragma unroll
    for (int i = 0; i < 32; i++) {
        int pos = i * 4 + ndt;
        float v = Cs[pos * 68 + c] + bb;
        gdst[pos * 64 + c] = v;
        sm += v; sq += v * v;
    }
    atomicAdd(&part[slot * 64 + c], sm);
    atomicAdd(&part[BN_PART * 64 + slot * 64 + c], sq);
}

// ---------------- conv1 (mma): x -> g_ht [b][n][s][c] + BN1 partials ----------------
__global__ void __launch_bounds__(256) k_conv1m(const float* __restrict__ x,
                                                const float* __restrict__ b1) {
    constexpr int K = 96, LD = K + 8;
    extern __shared__ char dsm[];
    __half* Bs = (__half*)dsm;                          // 64*104*2 = 13312
    __half* As = (__half*)(dsm + 13312);                // 128*104*2 = 26624
    float*  Cs = (float*)(dsm + 13312);                 // union, 34816
    __half* Xs = (__half*)(dsm + 13312 + 34816);        // 4*32*34*2 = 8704

    int bid = blockIdx.x;
    int b  = bid >> 8;
    int n0 = (bid & 255) * 4;
    int t  = threadIdx.x;

    // B load: g_W1h [c][96] -> Bs[c][LD]
    for (int i = t; i < 64 * (K / 2); i += 256) {        // u32 copies
        int c = i / (K / 2), o = i % (K / 2);
        *(unsigned*)(Bs + c * LD + o * 2) = *(const unsigned*)(g_W1h + c * K + o * 2);
    }
    // Xs: compact x tile fp16 with halo
    for (int i = t; i < 4 * 32; i += 256) { Xs[i * 34] = __float2half(0.f); Xs[i * 34 + 33] = __float2half(0.f); }
    for (int i = t; i < 1024; i += 256) {
        int nd = i >> 8, cin = (i >> 3) & 31, v = i & 7;
        float4 q = *(const float4*)(x + (((size_t)b * CIN + cin) * NN + (n0 + nd)) * SS + v * 4);
        __half* dr = Xs + (nd * 32 + cin) * 34 + 1 + v * 4;
        dr[0] = __float2half(q.x); dr[1] = __float2half(q.y);
        dr[2] = __float2half(q.z); dr[3] = __float2half(q.w);
    }
    __syncthreads();
    im2col<K, 32>(Xs, As, t);
    __syncthreads();
    conv_mma_core<K>(As, Bs, Cs, t);
    float* gdst = g_ht + ((size_t)b * NN + n0) * SS * 64;
    conv_epi(Cs, gdst, b1, g_bn1p, bid & (BN_PART - 1), t);
}

// ---------------- BN finalize ----------------
__global__ void k_bnfin(const float* __restrict__ g, const float* __restrict__ be,
                        int which, float inv_cnt) {
    int c = threadIdx.x;
    const float* part = (which == 0) ? g_bn1p : g_bn2p;
    float sm = 0.f, sq = 0.f;
    for (int s = 0; s < BN_PART; s++) {
        sm += part[s * 64 + c];
        sq += part[BN_PART * 64 + s * 64 + c];
    }
    float mean = sm * inv_cnt;
    float var  = sq * inv_cnt - mean * mean;
    float sc   = g[c] * rsqrtf(var + EPSV);
    if (which == 0) { g_sc1[c] = sc; g_sh1[c] = be[c] - mean * sc; }
    else            { g_sc2[c] = sc; g_sh2[c] = be[c] - mean * sc; }
}

// ---------------- hw (mma): relu(bn1(g_ht)) @ Wg -> g_hwh [b][s][n][d] fp16 ------------
__global__ void __launch_bounds__(256) k_hwm() {
    constexpr int K = 64, LD = K + 8;
    extern __shared__ char dsm[];
    __half* Bs = (__half*)dsm;                  // 64*72*2 = 9216
    __half* As = (__half*)(dsm + 9216);         // 128*72*2 = 18432
    float*  Cs = (float*)(dsm + 9216);          // union, 34816
    float*  scs = (float*)(dsm + 9216 + 34816); // 64
    float*  shs = scs + 64;

    int bid = blockIdx.x;
    int b  = bid >> 8;
    int n0 = (bid & 255) * 4;
    int t  = threadIdx.x;

    if (t < 64) { scs[t] = g_sc1[t]; shs[t] = g_sh1[t]; }
    for (int i = t; i < 64 * (K / 2); i += 256) {
        int c = i / (K / 2), o = i % (K / 2);
        *(unsigned*)(Bs + c * LD + o * 2) = *(const unsigned*)(g_Wgh + c * K + o * 2);
    }
    __syncthreads();
    const float* gsrc = g_ht + ((size_t)b * NN + n0) * SS * 64;
    for (int i = 0; i < 32; i++) {
        int idx = i * 256 + t;
        int pos = idx >> 6, c = idx & 63;
        float v = fmaxf(fmaf(gsrc[idx], scs[c], shs[c]), 0.f);
        As[pos * LD + c] = __float2half(v);
    }
    __syncthreads();
    conv_mma_core<K>(As, Bs, Cs, t);

    // Cs[pos][d] -> g_hwh[((b*SS+s)*NN+n)*64+d]
    for (int i = 0; i < 32; i++) {
        int idx = i * 256 + t;
        int pos = idx >> 6, d = idx & 63;
        int s = pos & 31, nd = pos >> 5;
        g_hwh[(((size_t)b * SS + s) * NN + (n0 + nd)) * CSP + d] =
            __float2half(Cs[pos * 68 + d]);
    }
}

// ---------------- GCN gather (half2) + bg + BN_s partials ----------------
__global__ void __launch_bounds__(256) k_gather(const float* __restrict__ bg) {
    int bid = blockIdx.x;
    int bs  = bid >> 7;
    int n0  = (bid & 127) * 8;
    int t   = threadIdx.x;
    int wr  = t >> 5, lane = t & 31;
    int n = n0 + wr, d = lane * 2;

    const __half* hws = g_hwh + (size_t)bs * NN * CSP;
    float di = g_dinv[n];
    float sl = di * di;
    float2 f0 = __half22float2(*(const __half2*)(hws + n * 64 + d));
    float ax = f0.x * sl, ay = f0.y * sl;

    int jb = g_rowptr[n], je = g_rowptr[n + 1];
    int j = jb;
    for (; j + 4 <= je; j += 4) {
        int c0 = g_col[j], c1 = g_col[j+1], c2 = g_col[j+2], c3 = g_col[j+3];
        float w0 = g_wgt[j], w1 = g_wgt[j+1], w2 = g_wgt[j+2], w3 = g_wgt[j+3];
        float2 a0 = __half22float2(*(const __half2*)(hws + c0 * 64 + d));
        float2 a1 = __half22float2(*(const __half2*)(hws + c1 * 64 + d));
        float2 a2 = __half22float2(*(const __half2*)(hws + c2 * 64 + d));
        float2 a3 = __half22float2(*(const __half2*)(hws + c3 * 64 + d));
        ax += a0.x*w0 + a1.x*w1 + a2.x*w2 + a3.x*w3;
        ay += a0.y*w0 + a1.y*w1 + a2.y*w2 + a3.y*w3;
    }
    for (; j < je; j++) {
        float w = g_wgt[j];
        float2 a = __half22float2(*(const __half2*)(hws + g_col[j] * 64 + d));
        ax += a.x * w; ay += a.y * w;
    }
    ax += bg[d]; ay += bg[d + 1];
    *(float2*)(g_agg + ((size_t)bs * NN + n) * CSP + d) = make_float2(ax, ay);

    __shared__ float red[8 * 64];
    red[wr * 64 + d] = ax; red[wr * 64 + d + 1] = ay;
    __syncthreads();
    if (t < 64) {
        float s1 = 0.f;
#pragma unroll
        for (int r = 0; r < 8; r++) s1 += red[r * 64 + t];
        atomicAdd(&g_bnssum[bs * 64 + t], s1);
    }
    __syncthreads();
    red[wr * 64 + d] = ax * ax; red[wr * 64 + d + 1] = ay * ay;
    __syncthreads();
    if (t < 64) {
        float s2 = 0.f;
#pragma unroll
        for (int r = 0; r < 8; r++) s2 += red[r * 64 + t];
        atomicAdd(&g_bnssq[bs * 64 + t], s2);
    }
}

// ---------------- BN_s finalize ----------------
__global__ void k_bnsfin(const float* __restrict__ gs, const float* __restrict__ bes) {
    int i = blockIdx.x * blockDim.x + threadIdx.x;
    if (i >= B * SS * CSP) return;
    int d = i & 63;
    float mean = g_bnssum[i] * (1.f / NN);
    float var  = g_bnssq[i] * (1.f / NN) - mean * mean;
    float sc   = gs[d] * rsqrtf(var + EPSV);
    g_scs[i] = sc;
    g_shs[i] = bes[d] - mean * sc;
}

// ---------------- conv2 (mma): relu(bns(g_agg)) -> g_h2t [b][n][s][c] + BN2 partials ----
__global__ void __launch_bounds__(256) k_conv2m(const float* __restrict__ b2) {
    constexpr int K = 192, LD = K + 8;
    extern __shared__ char dsm[];
    __half* Bs = (__half*)dsm;                          // 64*200*2 = 25600
    __half* As = (__half*)(dsm + 25600);                // 128*200*2 = 51200
    float*  Cs = (float*)(dsm + 25600);                 // union
    __half* Xs = (__half*)(dsm + 25600 + 51200);        // 4*64*34*2 = 17408

    int bid = blockIdx.x;
    int b  = bid >> 8;
    int n0 = (bid & 255) * 4;
    int t  = threadIdx.x;

    for (int i = t; i < 64 * (K / 2); i += 256) {
        int c = i / (K / 2), o = i % (K / 2);
        *(unsigned*)(Bs + c * LD + o * 2) = *(const unsigned*)(g_W2h + c * K + o * 2);
    }
    for (int i = t; i < 4 * 64; i += 256) { Xs[i * 34] = __float2half(0.f); Xs[i * 34 + 33] = __float2half(0.f); }
    for (int i = t; i < 8192; i += 256) {
        int d = i & 63, sidx = (i >> 6) & 31, nd = i >> 11;
        int bsi = b * SS + sidx;
        float v = g_agg[((size_t)bsi * NN + (n0 + nd)) * CSP + d];
        v = fmaxf(fmaf(v, g_scs[bsi * 64 + d], g_shs[bsi * 64 + d]), 0.f);
        Xs[(nd * 64 + d) * 34 + 1 + sidx] = __float2half(v);
    }
    __syncthreads();
    im2col<K, 64>(Xs, As, t);
    __syncthreads();
    conv_mma_core<K>(As, Bs, Cs, t);
    float* gdst = g_h2t + ((size_t)b * NN + n0) * SS * 64;
    conv_epi(Cs, gdst, b2, g_bn2p, bid & (BN_PART - 1), t);
}

// ---------------- output: relu( relu(bn2(h2)) + res ) -> out[b,c,n,s] ----------------
__global__ void __launch_bounds__(256) k_out(const float* __restrict__ x,
                                             const float* __restrict__ Wres,
                                             const float* __restrict__ bres,
                                             float* __restrict__ out) {
    extern __shared__ char dsm[];
    float* wrs = (float*)dsm;               // 32*64 = 8KB [cin][c]
    float* xs  = wrs + 2048;                // 4*32*32 = 16KB [node][cin][s]
    float* h2s = xs + 4096;                 // 128*68 = 34.8KB [pos][c]

    int bid = blockIdx.x;
    int b  = bid >> 8;
    int n0 = (bid & 255) * 4;
    int t  = threadIdx.x;

    for (int i = t; i < 2048; i += 256) {
        int c = i >> 5, cin = i & 31;
        wrs[cin * 64 + c] = Wres[i];
    }
    for (int i = t; i < 1024; i += 256) {
        int nd = i >> 8, cin = (i >> 3) & 31, v = i & 7;
        float4 q = *(const float4*)(x + (((size_t)b * CIN + cin) * NN + (n0 + nd)) * SS + v * 4);
        *(float4*)(xs + (nd * 32 + cin) * 32 + v * 4) = q;
    }
    const float* gsrc = g_h2t + ((size_t)b * NN + n0) * SS * 64;
    for (int i = 0; i < 32; i++) {
        int idx = i * 256 + t;
        h2s[(idx >> 6) * 68 + (idx & 63)] = gsrc[idx];
    }
    __syncthreads();

    int node = t >> 6, cg = (t >> 2) & 15, sq = t & 3;
    int c0 = cg * 4, s0 = sq * 8;
    float acc[4][8];
#pragma unroll
    for (int a = 0; a < 4; a++)
#pragma unroll
        for (int i = 0; i < 8; i++) acc[a][i] = 0.f;

    const float* xbase = xs + node * 32 * 32;
    for (int cin = 0; cin < CIN; cin++) {
        float4 w4 = *(float4*)(wrs + cin * 64 + c0);
        const float* xr = xbase + cin * 32 + s0;
        float4 x0 = *(const float4*)(xr);
        float4 x1 = *(const float4*)(xr + 4);
        float xv[8] = {x0.x, x0.y, x0.z, x0.w, x1.x, x1.y, x1.z, x1.w};
        float wv[4] = {w4.x, w4.y, w4.z, w4.w};
#pragma unroll
        for (int cc = 0; cc < 4; cc++)
#pragma unroll
            for (int i = 0; i < 8; i++)
                acc[cc][i] = fmaf(wv[cc], xv[i], acc[cc][i]);
    }

    int n = n0 + node;
#pragma unroll
    for (int cc = 0; cc < 4; cc++) {
        int c = c0 + cc;
        float sc = g_sc2[c], sh = g_sh2[c], br = bres[c];
        float o[8];
#pragma unroll
        for (int i = 0; i < 8; i++) {
            float hraw = h2s[(node * 32 + s0 + i) * 68 + c];
            float hv = fmaxf(fmaf(hraw, sc, sh), 0.f);
            o[i] = fmaxf(hv + acc[cc][i] + br, 0.f);
        }
        float* dst = out + (((size_t)b * COUT + c) * NN + n) * SS + s0;
        *(float4*)(dst)     = make_float4(o[0], o[1], o[2], o[3]);
        *(float4*)(dst + 4) = make_float4(o[4], o[5], o[6], o[7]);
    }
}

// ---------------- launch ----------------
extern "C" void kernel_launch(void* const* d_in, const int* in_sizes, int n_in,
                              void* d_out, int out_size) {
    const float* x    = (const float*)d_in[0];
    const int*   eiw  = (const int*)d_in[1];
    const float* W1   = (const float*)d_in[2];
    const float* b1   = (const float*)d_in[3];
    const float* g1   = (const float*)d_in[4];
    const float* be1  = (const float*)d_in[5];
    const float* Wg   = (const float*)d_in[6];
    const float* bg   = (const float*)d_in[7];
    const float* gs   = (const float*)d_in[8];
    const float* bes  = (const float*)d_in[9];
    const float* W2   = (const float*)d_in[10];
    const float* b2   = (const float*)d_in[11];
    const float* g2   = (const float*)d_in[12];
    const float* be2  = (const float*)d_in[13];
    const float* Wres = (const float*)d_in[14];
    const float* bres = (const float*)d_in[15];
    float*       out  = (float*)d_out;

    const int SM_C1 = 13312 + 34816 + 8704;            // 56832
    const int SM_C2 = 25600 + 51200 + 17408;           // 94208
    const int SM_HW = 9216 + 34816 + 512;              // 44544
    const int SM_OUT = (2048 + 4096 + 128 * 68) * 4;   // 59392
    cudaFuncSetAttribute(k_conv1m, cudaFuncAttributeMaxDynamicSharedMemorySize, SM_C1);
    cudaFuncSetAttribute(k_conv2m, cudaFuncAttributeMaxDynamicSharedMemorySize, SM_C2);
    cudaFuncSetAttribute(k_out,    cudaFuncAttributeMaxDynamicSharedMemorySize, SM_OUT);

    k_detect<<<1, 128>>>(eiw);
    k_zero<<<32, 256>>>();
    k_wt<<<48, 256>>>(W1, W2, Wg);
    k_conv1m<<<B * (NN / 4), 256, SM_C1>>>(x, b1);     // launch idx 3 -> profiled
    k_deg <<<EE / 256, 256>>>(eiw);
    k_scan<<<1, NN>>>();
    k_fill<<<EE / 256, 256>>>(eiw);
    k_bnfin<<<1, 64>>>(g1, be1, 0, 1.f / (float)(B * NN * SS));
    k_hwm<<<B * (NN / 4), 256, SM_HW>>>();
    k_gather<<<B * SS * (NN / 8), 256>>>(bg);
    k_bnsfin<<<32, 256>>>(gs, bes);
    k_conv2m<<<B * (NN / 4), 256, SM_C2>>>(b2);
    k_bnfin<<<1, 64>>>(g2, be2, 1, 1.f / (float)(B * NN * SS));
    k_out<<<B * (NN / 4), 256, SM_OUT>>>(x, Wres, bres, out);
}

// round 6
// speedup vs baseline: 2.3386x; 1.1018x over previous
#include <cuda_runtime.h>
#include <cuda_fp16.h>

// ---------------- problem constants ----------------
constexpr int B    = 4;
constexpr int CIN  = 32;
constexpr int NN   = 1024;
constexpr int SS   = 32;
constexpr int COUT = 64;
constexpr int CSP  = 64;
constexpr int EE   = 16384;
constexpr int BN_PART = 64;
constexpr float EPSV = 1e-5f;

// ---------------- device scratch ----------------
__device__ float  g_ht [B*NN*SS*COUT];   // conv1 raw [b][n][s][c]
__device__ __half g_hwh[B*SS*NN*CSP];    // projection [b][s][n][d] fp16
__device__ float  g_agg[B*SS*NN*CSP];    // gcn agg [b][s][n][d]
__device__ float  g_h2t[B*NN*SS*COUT];   // conv2 raw [b][n][s][c]

__device__ __half g_W1h[64*96];          // [c][tap*32+cin]
__device__ __half g_W2h[64*192];         // [c][tap*64+cin]
__device__ __half g_Wgh[64*64];          // Wg^T [d][c]

__device__ int   g_is64;
__device__ int   g_deg[NN];
__device__ int   g_fill[NN];
__device__ int   g_rowptr[NN+1];
__device__ int   g_col[EE];
__device__ float g_wgt[EE];
__device__ float g_dinv[NN];

__device__ float g_bn1p[2*BN_PART*COUT];
__device__ float g_bn2p[2*BN_PART*COUT];
__device__ float g_bnssum[B*SS*CSP];
__device__ float g_bnssq [B*SS*CSP];
__device__ float g_sc1[COUT], g_sh1[COUT];
__device__ float g_sc2[COUT], g_sh2[COUT];
__device__ float g_scs[B*SS*CSP], g_shs[B*SS*CSP];

// ---------------- mma helpers ----------------
__device__ __forceinline__ unsigned su32(const void* p) {
    return (unsigned)__cvta_generic_to_shared(p);
}
__device__ __forceinline__ void ldmA(unsigned addr, unsigned& a0, unsigned& a1,
                                     unsigned& a2, unsigned& a3) {
    asm volatile("ldmatrix.sync.aligned.m8n8.x4.shared.b16 {%0,%1,%2,%3}, [%4];"
                 : "=r"(a0), "=r"(a1), "=r"(a2), "=r"(a3) : "r"(addr));
}
__device__ __forceinline__ void ldmB(unsigned addr, unsigned& b0, unsigned& b1) {
    asm volatile("ldmatrix.sync.aligned.m8n8.x2.shared.b16 {%0,%1}, [%2];"
                 : "=r"(b0), "=r"(b1) : "r"(addr));
}
__device__ __forceinline__ void mma16816(float* c, unsigned a0, unsigned a1,
                                         unsigned a2, unsigned a3,
                                         unsigned b0, unsigned b1) {
    asm volatile("mma.sync.aligned.m16n8k16.row.col.f32.f16.f16.f32 "
                 "{%0,%1,%2,%3},{%4,%5,%6,%7},{%8,%9},{%0,%1,%2,%3};"
                 : "+f"(c[0]), "+f"(c[1]), "+f"(c[2]), "+f"(c[3])
                 : "r"(a0), "r"(a1), "r"(a2), "r"(a3), "r"(b0), "r"(b1));
}

// ---------------- prep: detect dtype + zero + weight convert/relayout ----------------
__global__ void k_prep(const int* __restrict__ w, const float* __restrict__ W1,
                       const float* __restrict__ W2, const float* __restrict__ Wg) {
    int t = threadIdx.x;
    int gid = blockIdx.x * 256 + t;
    if (blockIdx.x == 0) {
        __shared__ int s_any;
        if (t == 0) s_any = 0;
        __syncthreads();
        if (w[2 * (t * 64) + 1] != 0) atomicOr(&s_any, 1);
        __syncthreads();
        if (t == 0) g_is64 = s_any ? 0 : 1;
    }
    if (gid < NN) { g_deg[gid] = 0; g_fill[gid] = 0; }
    if (gid < 2*BN_PART*COUT) { g_bn1p[gid] = 0.f; g_bn2p[gid] = 0.f; }
    if (gid < B*SS*CSP) { g_bnssum[gid] = 0.f; g_bnssq[gid] = 0.f; }
    if (gid < 64*96) {   // [c][tap*32+cin] <- W1[c][cin*3+tap]
        int c = gid / 96, r = gid % 96, tap = r >> 5, cin = r & 31;
        g_W1h[gid] = __float2half(W1[c * 96 + cin * 3 + tap]);
    }
    if (gid < 64*192) {  // [c][tap*64+cin] <- W2[c][cin*3+tap]
        int c = gid / 192, r = gid % 192, tap = r >> 6, cin = r & 63;
        g_W2h[gid] = __float2half(W2[c * 192 + cin * 3 + tap]);
    }
    if (gid < 64*64)     // [d][c]
        g_Wgh[gid] = __float2half(Wg[(gid & 63) * 64 + (gid >> 6)]);
}

// ---------------- degree / scan / fill ----------------
__global__ void k_deg(const int* __restrict__ w) {
    int e = blockIdx.x * blockDim.x + threadIdx.x;
    if (e >= EE) return;
    int stride = g_is64 ? 2 : 1;
    int d = w[stride * (EE + e)];
    if ((unsigned)d < (unsigned)NN) atomicAdd(&g_deg[d], 1);
}
__global__ void k_scan() {
    __shared__ int sh[NN];
    int t = threadIdx.x;
    int c = g_deg[t];
    g_dinv[t] = rsqrtf((float)(c + 1));
    sh[t] = c;
    __syncthreads();
    for (int off = 1; off < NN; off <<= 1) {
        int v = (t >= off) ? sh[t - off] : 0;
        __syncthreads();
        sh[t] += v;
        __syncthreads();
    }
    g_rowptr[t + 1] = sh[t];
    if (t == 0) g_rowptr[0] = 0;
}
__global__ void k_fill(const int* __restrict__ w) {
    int e = blockIdx.x * blockDim.x + threadIdx.x;
    if (e >= EE) return;
    int stride = g_is64 ? 2 : 1;
    int s = w[stride * e];
    int d = w[stride * (EE + e)];
    if ((unsigned)s >= (unsigned)NN || (unsigned)d >= (unsigned)NN) return;
    int pos = atomicAdd(&g_fill[d], 1);
    int j = g_rowptr[d] + pos;
    g_col[j] = s;
    g_wgt[j] = g_dinv[s] * g_dinv[d];
}

// ========== tapped tensor-core conv core: X smem [nd][34][CINT] stride LDX ==========
// 3 taps x (CINT/16) kblocks, accumulate; write Cs[pos][c] stride 68.
template<int CINT, int LDX, int LDB>
__device__ __forceinline__ void conv_tap_mma(const __half* Xs, const __half* Bs,
                                             float* Cs, int t) {
    int wm = t >> 5, lane = t & 31;
    int nd = wm >> 1;
    int sLoc = (wm & 1) * 16 + (lane & 15);
    float acc[8][4];
#pragma unroll
    for (int nt = 0; nt < 8; nt++)
#pragma unroll
        for (int i = 0; i < 4; i++) acc[nt][i] = 0.f;

    unsigned xb = su32(Xs);
    unsigned bb = su32(Bs) + ((lane & 7) * LDB + ((lane >> 3) & 1) * 8) * 2;
#pragma unroll
    for (int tap = 0; tap < 3; tap++) {
        unsigned aBase = xb + ((nd * 34 + sLoc + tap) * LDX + (lane >> 4) * 8) * 2;
#pragma unroll
        for (int kb = 0; kb < CINT / 16; kb++) {
            unsigned a0, a1, a2, a3;
            ldmA(aBase + kb * 32, a0, a1, a2, a3);
            unsigned bOff = (tap * CINT + kb * 16) * 2;
#pragma unroll
            for (int nt = 0; nt < 8; nt++) {
                unsigned b0, b1;
                ldmB(bb + (unsigned)(nt * 8 * LDB) * 2 + bOff, b0, b1);
                mma16816(acc[nt], a0, a1, a2, a3, b0, b1);
            }
        }
    }
#pragma unroll
    for (int nt = 0; nt < 8; nt++) {
        int r0 = wm * 16 + (lane >> 2);
        int col = nt * 8 + (lane & 3) * 2;
        *(float2*)&Cs[r0 * 68 + col]       = make_float2(acc[nt][0], acc[nt][1]);
        *(float2*)&Cs[(r0 + 8) * 68 + col] = make_float2(acc[nt][2], acc[nt][3]);
    }
    __syncthreads();
}

// epilogue: Cs[pos][c]+bias -> gdst[pos*64+c], BN partials
__device__ __forceinline__ void conv_epi(const float* Cs, float* gdst,
                                         const float* __restrict__ bias,
                                         float* part, int slot, int t) {
    int c = t & 63, ndt = t >> 6;
    float bb = bias[c];
    float sm = 0.f, sq = 0.f;
#pragma unroll
    for (int i = 0; i < 32; i++) {
        int pos = i * 4 + ndt;
        float v = Cs[pos * 68 + c] + bb;
        gdst[pos * 64 + c] = v;
        sm += v; sq += v * v;
    }
    atomicAdd(&part[slot * 64 + c], sm);
    atomicAdd(&part[BN_PART * 64 + slot * 64 + c], sq);
}

// ---------------- conv1 (tap-mma): x -> g_ht + BN1 partials ----------------
__global__ void __launch_bounds__(256) k_conv1m(const float* __restrict__ x,
                                                const float* __restrict__ b1) {
    constexpr int LDX = 40, LDB = 104;
    extern __shared__ char dsm[];
    __half* Bs = (__half*)dsm;                     // 64*104*2 = 13312
    __half* Xs = (__half*)(dsm + 13312);           // 4*34*40*2 = 10880
    float*  Cs = (float*)(dsm + 13312 + 10880);    // 128*68*4 = 34816

    int bid = blockIdx.x;
    int b  = bid >> 8;
    int n0 = (bid & 255) * 4;
    int t  = threadIdx.x;

    for (int i = t; i < 64 * 48; i += 256) {       // u32 copies of [c][96]
        int c = i / 48, o = i % 48;
        *(unsigned*)(Bs + c * LDB + o * 2) = *(const unsigned*)(g_W1h + c * 96 + o * 2);
    }
    if (t < 128) {                                  // zero halo rows
        int nd = t >> 5, r = (t >> 4) & 1, cp = t & 15;
        *(__half2*)(Xs + (nd * 34 + r * 33) * LDX + cp * 2) = __half2half2(__float2half(0.f));
    }
    {                                               // X fill: [nd][1+s][cin] half2
        int i = t;                                  // 512 items, 2 iters
#pragma unroll
        for (int it = 0; it < 2; it++, i += 256) {
            int nd = i >> 7, cp = (i >> 3) & 15, v = i & 7;
            const float* xb0 = x + (((size_t)b * CIN + 2*cp)     * NN + (n0 + nd)) * SS + v * 4;
            const float* xb1 = x + (((size_t)b * CIN + 2*cp + 1) * NN + (n0 + nd)) * SS + v * 4;
            float4 q0 = *(const float4*)xb0;
            float4 q1 = *(const float4*)xb1;
            __half* dst = Xs + (nd * 34 + 1 + v * 4) * LDX + cp * 2;
            *(__half2*)(dst)           = __floats2half2_rn(q0.x, q1.x);
            *(__half2*)(dst + LDX)     = __floats2half2_rn(q0.y, q1.y);
            *(__half2*)(dst + 2 * LDX) = __floats2half2_rn(q0.z, q1.z);
            *(__half2*)(dst + 3 * LDX) = __floats2half2_rn(q0.w, q1.w);
        }
    }
    __syncthreads();
    conv_tap_mma<32, LDX, LDB>(Xs, Bs, Cs, t);
    float* gdst = g_ht + ((size_t)b * NN + n0) * SS * 64;
    conv_epi(Cs, gdst, b1, g_bn1p, bid & (BN_PART - 1), t);
}

// ---------------- BN finalize ----------------
__global__ void k_bnfin(const float* __restrict__ g, const float* __restrict__ be,
                        int which, float inv_cnt) {
    int c = threadIdx.x;
    const float* part = (which == 0) ? g_bn1p : g_bn2p;
    float sm = 0.f, sq = 0.f;
    for (int s = 0; s < BN_PART; s++) {
        sm += part[s * 64 + c];
        sq += part[BN_PART * 64 + s * 64 + c];
    }
    float mean = sm * inv_cnt;
    float var  = sq * inv_cnt - mean * mean;
    float sc   = g[c] * rsqrtf(var + EPSV);
    if (which == 0) { g_sc1[c] = sc; g_sh1[c] = be[c] - mean * sc; }
    else            { g_sc2[c] = sc; g_sh2[c] = be[c] - mean * sc; }
}

// ---------------- hw (mma): relu(bn1(g_ht)) @ Wg -> g_hwh fp16 ----------------
__global__ void __launch_bounds__(256) k_hwm() {
    constexpr int LD = 72;
    extern __shared__ char dsm[];
    __half* Bs = (__half*)dsm;                  // 64*72*2 = 9216
    __half* As = (__half*)(dsm + 9216);         // 128*72*2 = 18432
    float*  Cs = (float*)(dsm + 9216);          // union with As: 34816
    float*  scs = (float*)(dsm + 9216 + 34816);
    float*  shs = scs + 64;

    int bid = blockIdx.x;
    int b  = bid >> 8;
    int n0 = (bid & 255) * 4;
    int t  = threadIdx.x;

    if (t < 64) { scs[t] = g_sc1[t]; shs[t] = g_sh1[t]; }
    for (int i = t; i < 64 * 32; i += 256) {
        int c = i / 32, o = i % 32;
        *(unsigned*)(Bs + c * LD + o * 2) = *(const unsigned*)(g_Wgh + c * 64 + o * 2);
    }
    __syncthreads();
    const float* gsrc = g_ht + ((size_t)b * NN + n0) * SS * 64;
#pragma unroll
    for (int it = 0; it < 16; it++) {
        int i = it * 256 + t;
        int pos = i >> 5, dp = i & 31;
        float2 v = *(const float2*)(gsrc + pos * 64 + dp * 2);
        float a = fmaxf(fmaf(v.x, scs[dp*2],   shs[dp*2]),   0.f);
        float bv = fmaxf(fmaf(v.y, scs[dp*2+1], shs[dp*2+1]), 0.f);
        *(__half2*)(As + pos * LD + dp * 2) = __floats2half2_rn(a, bv);
    }
    __syncthreads();

    // plain GEMM K=64
    {
        int wm = t >> 5, lane = t & 31;
        float acc[8][4];
#pragma unroll
        for (int nt = 0; nt < 8; nt++)
#pragma unroll
            for (int i = 0; i < 4; i++) acc[nt][i] = 0.f;
        unsigned aBase = su32(As) + ((wm * 16 + (lane & 15)) * LD + (lane >> 4) * 8) * 2;
        unsigned bBase = su32(Bs) + ((lane & 7) * LD + ((lane >> 3) & 1) * 8) * 2;
#pragma unroll
        for (int kb = 0; kb < 4; kb++) {
            unsigned a0, a1, a2, a3;
            ldmA(aBase + kb * 32, a0, a1, a2, a3);
#pragma unroll
            for (int nt = 0; nt < 8; nt++) {
                unsigned b0, b1;
                ldmB(bBase + (unsigned)(nt * 8 * LD) * 2 + kb * 32, b0, b1);
                mma16816(acc[nt], a0, a1, a2, a3, b0, b1);
            }
        }
        __syncthreads();   // As dead before Cs write
#pragma unroll
        for (int nt = 0; nt < 8; nt++) {
            int r0 = wm * 16 + (lane >> 2);
            int col = nt * 8 + (lane & 3) * 2;
            *(float2*)&Cs[r0 * 68 + col]       = make_float2(acc[nt][0], acc[nt][1]);
            *(float2*)&Cs[(r0 + 8) * 68 + col] = make_float2(acc[nt][2], acc[nt][3]);
        }
        __syncthreads();
    }
#pragma unroll
    for (int it = 0; it < 32; it++) {
        int idx = it * 256 + t;
        int pos = idx >> 6, d = idx & 63;
        int s = pos & 31, nd = pos >> 5;
        g_hwh[(((size_t)b * SS + s) * NN + (n0 + nd)) * CSP + d] =
            __float2half(Cs[pos * 68 + d]);
    }
}

// ---------------- GCN gather (half2) + bg + BN_s partials ----------------
__global__ void __launch_bounds__(256) k_gather(const float* __restrict__ bg) {
    int bid = blockIdx.x;
    int bs  = bid >> 7;
    int n0  = (bid & 127) * 8;
    int t   = threadIdx.x;
    int wr  = t >> 5, lane = t & 31;
    int n = n0 + wr, d = lane * 2;

    const __half* hws = g_hwh + (size_t)bs * NN * CSP;
    float di = g_dinv[n];
    float sl = di * di;
    float2 f0 = __half22float2(*(const __half2*)(hws + n * 64 + d));
    float ax = f0.x * sl, ay = f0.y * sl;

    int jb = g_rowptr[n], je = g_rowptr[n + 1];
    int j = jb;
    for (; j + 4 <= je; j += 4) {
        int c0 = g_col[j], c1 = g_col[j+1], c2 = g_col[j+2], c3 = g_col[j+3];
        float w0 = g_wgt[j], w1 = g_wgt[j+1], w2 = g_wgt[j+2], w3 = g_wgt[j+3];
        float2 a0 = __half22float2(*(const __half2*)(hws + c0 * 64 + d));
        float2 a1 = __half22float2(*(const __half2*)(hws + c1 * 64 + d));
        float2 a2 = __half22float2(*(const __half2*)(hws + c2 * 64 + d));
        float2 a3 = __half22float2(*(const __half2*)(hws + c3 * 64 + d));
        ax += a0.x*w0 + a1.x*w1 + a2.x*w2 + a3.x*w3;
        ay += a0.y*w0 + a1.y*w1 + a2.y*w2 + a3.y*w3;
    }
    for (; j < je; j++) {
        float w = g_wgt[j];
        float2 a = __half22float2(*(const __half2*)(hws + g_col[j] * 64 + d));
        ax += a.x * w; ay += a.y * w;
    }
    ax += bg[d]; ay += bg[d + 1];
    *(float2*)(g_agg + ((size_t)bs * NN + n) * CSP + d) = make_float2(ax, ay);

    __shared__ float red[8 * 64];
    red[wr * 64 + d] = ax; red[wr * 64 + d + 1] = ay;
    __syncthreads();
    if (t < 64) {
        float s1 = 0.f;
#pragma unroll
        for (int r = 0; r < 8; r++) s1 += red[r * 64 + t];
        atomicAdd(&g_bnssum[bs * 64 + t], s1);
    }
    __syncthreads();
    red[wr * 64 + d] = ax * ax; red[wr * 64 + d + 1] = ay * ay;
    __syncthreads();
    if (t < 64) {
        float s2 = 0.f;
#pragma unroll
        for (int r = 0; r < 8; r++) s2 += red[r * 64 + t];
        atomicAdd(&g_bnssq[bs * 64 + t], s2);
    }
}

// ---------------- BN_s finalize ----------------
__global__ void k_bnsfin(const float* __restrict__ gs, const float* __restrict__ bes) {
    int i = blockIdx.x * blockDim.x + threadIdx.x;
    if (i >= B * SS * CSP) return;
    int d = i & 63;
    float mean = g_bnssum[i] * (1.f / NN);
    float var  = g_bnssq[i] * (1.f / NN) - mean * mean;
    float sc   = gs[d] * rsqrtf(var + EPSV);
    g_scs[i] = sc;
    g_shs[i] = bes[d] - mean * sc;
}

// ---------------- conv2 (tap-mma): relu(bns(g_agg)) -> g_h2t + BN2 partials ----------
__global__ void __launch_bounds__(256) k_conv2m(const float* __restrict__ b2) {
    constexpr int LDX = 72, LDB = 200;
    extern __shared__ char dsm[];
    __half* Bs = (__half*)dsm;                     // 64*200*2 = 25600
    __half* Xs = (__half*)(dsm + 25600);           // 4*34*72*2 = 19584
    float*  Cs = (float*)(dsm + 25600 + 19584);    // 34816

    int bid = blockIdx.x;
    int b  = bid >> 8;
    int n0 = (bid & 255) * 4;
    int t  = threadIdx.x;

    for (int i = t; i < 64 * 96; i += 256) {
        int c = i / 96, o = i % 96;
        *(unsigned*)(Bs + c * LDB + o * 2) = *(const unsigned*)(g_W2h + c * 192 + o * 2);
    }
    if (t < 256) {                                  // zero halo rows (4nd x 2r x 32 half2)
        int nd = t >> 6, r = (t >> 5) & 1, cp = t & 31;
        *(__half2*)(Xs + (nd * 34 + r * 33) * LDX + cp * 2) = __half2half2(__float2half(0.f));
    }
#pragma unroll
    for (int it = 0; it < 16; it++) {               // 4096 half2 items
        int i = it * 256 + t;
        int nd = i >> 10, sidx = (i >> 5) & 31, dp = i & 31;
        int bsi = b * SS + sidx;
        float2 v = *(const float2*)(g_agg + ((size_t)bsi * NN + (n0 + nd)) * CSP + dp * 2);
        float2 sc = *(const float2*)(g_scs + bsi * 64 + dp * 2);
        float2 sh = *(const float2*)(g_shs + bsi * 64 + dp * 2);
        float a = fmaxf(fmaf(v.x, sc.x, sh.x), 0.f);
        float bv = fmaxf(fmaf(v.y, sc.y, sh.y), 0.f);
        *(__half2*)(Xs + (nd * 34 + 1 + sidx) * LDX + dp * 2) = __floats2half2_rn(a, bv);
    }
    __syncthreads();
    conv_tap_mma<64, LDX, LDB>(Xs, Bs, Cs, t);
    float* gdst = g_h2t + ((size_t)b * NN + n0) * SS * 64;
    conv_epi(Cs, gdst, b2, g_bn2p, bid & (BN_PART - 1), t);
}

// ---------------- output: relu( relu(bn2(h2)) + res ) -> out[b,c,n,s] ----------------
__global__ void __launch_bounds__(256) k_out(const float* __restrict__ x,
                                             const float* __restrict__ Wres,
                                             const float* __restrict__ bres,
                                             float* __restrict__ out) {
    extern __shared__ char dsm[];
    float* wrs = (float*)dsm;               // 32*64 [cin][c]
    float* xs  = wrs + 2048;                // 4*32*32 [node][cin][s]
    float* h2s = xs + 4096;                 // 128*68 [pos][c]

    int bid = blockIdx.x;
    int b  = bid >> 8;
    int n0 = (bid & 255) * 4;
    int t  = threadIdx.x;

    for (int i = t; i < 2048; i += 256) {
        int c = i >> 5, cin = i & 31;
        wrs[cin * 64 + c] = Wres[i];
    }
    for (int i = t; i < 1024; i += 256) {
        int nd = i >> 8, cin = (i >> 3) & 31, v = i & 7;
        float4 q = *(const float4*)(x + (((size_t)b * CIN + cin) * NN + (n0 + nd)) * SS + v * 4);
        *(float4*)(xs + (nd * 32 + cin) * 32 + v * 4) = q;
    }
    const float* gsrc = g_h2t + ((size_t)b * NN + n0) * SS * 64;
#pragma unroll
    for (int i = 0; i < 32; i++) {
        int idx = i * 256 + t;
        h2s[(idx >> 6) * 68 + (idx & 63)] = gsrc[idx];
    }
    __syncthreads();

    int node = t >> 6, cg = (t >> 2) & 15, sq = t & 3;
    int c0 = cg * 4, s0 = sq * 8;
    float acc[4][8];
#pragma unroll
    for (int a = 0; a < 4; a++)
#pragma unroll
        for (int i = 0; i < 8; i++) acc[a][i] = 0.f;

    const float* xbase = xs + node * 32 * 32;
    for (int cin = 0; cin < CIN; cin++) {
        float4 w4 = *(float4*)(wrs + cin * 64 + c0);
        const float* xr = xbase + cin * 32 + s0;
        float4 x0 = *(const float4*)(xr);
        float4 x1 = *(const float4*)(xr + 4);
        float xv[8] = {x0.x, x0.y, x0.z, x0.w, x1.x, x1.y, x1.z, x1.w};
        float wv[4] = {w4.x, w4.y, w4.z, w4.w};
#pragma unroll
        for (int cc = 0; cc < 4; cc++)
#pragma unroll
            for (int i = 0; i < 8; i++)
                acc[cc][i] = fmaf(wv[cc], xv[i], acc[cc][i]);
    }

    int n = n0 + node;
#pragma unroll
    for (int cc = 0; cc < 4; cc++) {
        int c = c0 + cc;
        float sc = g_sc2[c], sh = g_sh2[c], br = bres[c];
        float o[8];
#pragma unroll
        for (int i = 0; i < 8; i++) {
            float hraw = h2s[(node * 32 + s0 + i) * 68 + c];
            float hv = fmaxf(fmaf(hraw, sc, sh), 0.f);
            o[i] = fmaxf(hv + acc[cc][i] + br, 0.f);
        }
        float* dst = out + (((size_t)b * COUT + c) * NN + n) * SS + s0;
        *(float4*)(dst)     = make_float4(o[0], o[1], o[2], o[3]);
        *(float4*)(dst + 4) = make_float4(o[4], o[5], o[6], o[7]);
    }
}

// ---------------- launch ----------------
extern "C" void kernel_launch(void* const* d_in, const int* in_sizes, int n_in,
                              void* d_out, int out_size) {
    const float* x    = (const float*)d_in[0];
    const int*   eiw  = (const int*)d_in[1];
    const float* W1   = (const float*)d_in[2];
    const float* b1   = (const float*)d_in[3];
    const float* g1   = (const float*)d_in[4];
    const float* be1  = (const float*)d_in[5];
    const float* Wg   = (const float*)d_in[6];
    const float* bg   = (const float*)d_in[7];
    const float* gs   = (const float*)d_in[8];
    const float* bes  = (const float*)d_in[9];
    const float* W2   = (const float*)d_in[10];
    const float* b2   = (const float*)d_in[11];
    const float* g2   = (const float*)d_in[12];
    const float* be2  = (const float*)d_in[13];
    const float* Wres = (const float*)d_in[14];
    const float* bres = (const float*)d_in[15];
    float*       out  = (float*)d_out;

    const int SM_C1 = 13312 + 10880 + 34816;            // 59008
    const int SM_C2 = 25600 + 19584 + 34816;            // 80000
    const int SM_HW = 9216 + 34816 + 512;               // 44544
    const int SM_OUT = (2048 + 4096 + 128 * 68) * 4;    // 59392
    cudaFuncSetAttribute(k_conv1m, cudaFuncAttributeMaxDynamicSharedMemorySize, SM_C1);
    cudaFuncSetAttribute(k_conv2m, cudaFuncAttributeMaxDynamicSharedMemorySize, SM_C2);
    cudaFuncSetAttribute(k_out,    cudaFuncAttributeMaxDynamicSharedMemorySize, SM_OUT);

    k_prep<<<48, 256>>>(eiw, W1, W2, Wg);
    k_conv1m<<<B * (NN / 4), 256, SM_C1>>>(x, b1);
    k_deg <<<EE / 256, 256>>>(eiw);
    k_scan<<<1, NN>>>();
    k_fill<<<EE / 256, 256>>>(eiw);
    k_bnfin<<<1, 64>>>(g1, be1, 0, 1.f / (float)(B * NN * SS));
    k_hwm<<<B * (NN / 4), 256, SM_HW>>>();
    k_gather<<<B * SS * (NN / 8), 256>>>(bg);
    k_bnsfin<<<32, 256>>>(gs, bes);
    k_conv2m<<<B * (NN / 4), 256, SM_C2>>>(b2);
    k_bnfin<<<1, 64>>>(g2, be2, 1, 1.f / (float)(B * NN * SS));
    k_out<<<B * (NN / 4), 256, SM_OUT>>>(x, Wres, bres, out);
}

// round 8
// speedup vs baseline: 2.4133x; 1.0320x over previous
#include <cuda_runtime.h>
#include <cuda_fp16.h>

// ---------------- problem constants ----------------
constexpr int B    = 4;
constexpr int CIN  = 32;
constexpr int NN   = 1024;
constexpr int SS   = 32;
constexpr int COUT = 64;
constexpr int CSP  = 64;
constexpr int EE   = 16384;
constexpr int BN_PART = 64;
constexpr float EPSV = 1e-5f;
constexpr float INV_CNT = 1.f / (float)(B * NN * SS);

// ---------------- device scratch ----------------
__device__ float  g_ht [B*NN*SS*COUT];   // conv1 raw [b][n][s][c]
__device__ __half g_hwh[B*SS*NN*CSP];    // projection [b][s][n][d] fp16
__device__ float  g_agg[B*SS*NN*CSP];    // gcn agg [b][s][n][d]
__device__ float  g_h2t[B*NN*SS*COUT];   // conv2 raw [b][n][s][c]

__device__ __half g_W1h[64*96];          // [c][tap*32+cin]
__device__ __half g_W2h[64*192];         // [c][tap*64+cin]
__device__ __half g_Wgh[64*64];          // Wg^T [d][c]

__device__ int   g_is64;
__device__ int   g_deg[NN];
__device__ int   g_fill[NN];
__device__ int   g_rowptr[NN+1];
__device__ int   g_col[EE];
__device__ float g_wgt[EE];
__device__ float g_dinv[NN];

__device__ float g_bn1p[2*BN_PART*COUT];
__device__ float g_bn2p[2*BN_PART*COUT];
__device__ float g_bnssum[B*SS*CSP];
__device__ float g_bnssq [B*SS*CSP];

// ---------------- mma helpers ----------------
__device__ __forceinline__ unsigned su32(const void* p) {
    return (unsigned)__cvta_generic_to_shared(p);
}
__device__ __forceinline__ void ldmA(unsigned addr, unsigned& a0, unsigned& a1,
                                     unsigned& a2, unsigned& a3) {
    asm volatile("ldmatrix.sync.aligned.m8n8.x4.shared.b16 {%0,%1,%2,%3}, [%4];"
                 : "=r"(a0), "=r"(a1), "=r"(a2), "=r"(a3) : "r"(addr));
}
__device__ __forceinline__ void ldmB(unsigned addr, unsigned& b0, unsigned& b1) {
    asm volatile("ldmatrix.sync.aligned.m8n8.x2.shared.b16 {%0,%1}, [%2];"
                 : "=r"(b0), "=r"(b1) : "r"(addr));
}
__device__ __forceinline__ void mma16816(float* c, unsigned a0, unsigned a1,
                                         unsigned a2, unsigned a3,
                                         unsigned b0, unsigned b1) {
    asm volatile("mma.sync.aligned.m16n8k16.row.col.f32.f16.f16.f32 "
                 "{%0,%1,%2,%3},{%4,%5,%6,%7},{%8,%9},{%0,%1,%2,%3};"
                 : "+f"(c[0]), "+f"(c[1]), "+f"(c[2]), "+f"(c[3])
                 : "r"(a0), "r"(a1), "r"(a2), "r"(a3), "r"(b0), "r"(b1));
}

// ---------------- prep: detect dtype + zero + weight convert/relayout ----------------
__global__ void k_prep(const int* __restrict__ w, const float* __restrict__ W1,
                       const float* __restrict__ W2, const float* __restrict__ Wg) {
    int t = threadIdx.x;
    int gid = blockIdx.x * 256 + t;
    if (blockIdx.x == 0) {
        __shared__ int s_any;
        if (t == 0) s_any = 0;
        __syncthreads();
        if (w[2 * (t * 64) + 1] != 0) atomicOr(&s_any, 1);
        __syncthreads();
        if (t == 0) g_is64 = s_any ? 0 : 1;
    }
    if (gid < NN) { g_deg[gid] = 0; g_fill[gid] = 0; }
    if (gid < 2*BN_PART*COUT) { g_bn1p[gid] = 0.f; g_bn2p[gid] = 0.f; }
    if (gid < B*SS*CSP) { g_bnssum[gid] = 0.f; g_bnssq[gid] = 0.f; }
    if (gid < 64*96) {
        int c = gid / 96, r = gid % 96, tap = r >> 5, cin = r & 31;
        g_W1h[gid] = __float2half(W1[c * 96 + cin * 3 + tap]);
    }
    if (gid < 64*192) {
        int c = gid / 192, r = gid % 192, tap = r >> 6, cin = r & 63;
        g_W2h[gid] = __float2half(W2[c * 192 + cin * 3 + tap]);
    }
    if (gid < 64*64)
        g_Wgh[gid] = __float2half(Wg[(gid & 63) * 64 + (gid >> 6)]);
}

// ---------------- degree / scan / fill ----------------
__global__ void k_deg(const int* __restrict__ w) {
    int e = blockIdx.x * blockDim.x + threadIdx.x;
    if (e >= EE) return;
    int stride = g_is64 ? 2 : 1;
    int d = w[stride * (EE + e)];
    if ((unsigned)d < (unsigned)NN) atomicAdd(&g_deg[d], 1);
}
__global__ void k_scan() {
    int t = threadIdx.x, lane = t & 31, wid = t >> 5;
    int c = g_deg[t];
    g_dinv[t] = rsqrtf((float)(c + 1));
    int v = c;
#pragma unroll
    for (int o = 1; o < 32; o <<= 1) {
        int u = __shfl_up_sync(0xffffffffu, v, o);
        if (lane >= o) v += u;
    }
    __shared__ int wsum[32];
    if (lane == 31) wsum[wid] = v;
    __syncthreads();
    if (wid == 0) {
        int wv = wsum[lane];
#pragma unroll
        for (int o = 1; o < 32; o <<= 1) {
            int u = __shfl_up_sync(0xffffffffu, wv, o);
            if (lane >= o) wv += u;
        }
        wsum[lane] = wv;
    }
    __syncthreads();
    int off = (wid > 0) ? wsum[wid - 1] : 0;
    g_rowptr[t + 1] = off + v;
    if (t == 0) g_rowptr[0] = 0;
}
__global__ void k_fill(const int* __restrict__ w) {
    int e = blockIdx.x * blockDim.x + threadIdx.x;
    if (e >= EE) return;
    int stride = g_is64 ? 2 : 1;
    int s = w[stride * e];
    int d = w[stride * (EE + e)];
    if ((unsigned)s >= (unsigned)NN || (unsigned)d >= (unsigned)NN) return;
    int pos = atomicAdd(&g_fill[d], 1);
    int j = g_rowptr[d] + pos;
    g_col[j] = s;
    g_wgt[j] = g_dinv[s] * g_dinv[d];
}

// ========== tapped tensor-core conv core ==========
template<int CINT, int LDX, int LDB>
__device__ __forceinline__ void conv_tap_mma(const __half* Xs, const __half* Bs,
                                             float* Cs, int t) {
    int wm = t >> 5, lane = t & 31;
    int nd = wm >> 1;
    int sLoc = (wm & 1) * 16 + (lane & 15);
    float acc[8][4];
#pragma unroll
    for (int nt = 0; nt < 8; nt++)
#pragma unroll
        for (int i = 0; i < 4; i++) acc[nt][i] = 0.f;

    unsigned xb = su32(Xs);
    unsigned bb = su32(Bs) + ((lane & 7) * LDB + ((lane >> 3) & 1) * 8) * 2;
#pragma unroll
    for (int tap = 0; tap < 3; tap++) {
        unsigned aBase = xb + ((nd * 34 + sLoc + tap) * LDX + (lane >> 4) * 8) * 2;
#pragma unroll
        for (int kb = 0; kb < CINT / 16; kb++) {
            unsigned a0, a1, a2, a3;
            ldmA(aBase + kb * 32, a0, a1, a2, a3);
            unsigned bOff = (tap * CINT + kb * 16) * 2;
#pragma unroll
            for (int nt = 0; nt < 8; nt++) {
                unsigned b0, b1;
                ldmB(bb + (unsigned)(nt * 8 * LDB) * 2 + bOff, b0, b1);
                mma16816(acc[nt], a0, a1, a2, a3, b0, b1);
            }
        }
    }
#pragma unroll
    for (int nt = 0; nt < 8; nt++) {
        int r0 = wm * 16 + (lane >> 2);
        int col = nt * 8 + (lane & 3) * 2;
        *(float2*)&Cs[r0 * 68 + col]       = make_float2(acc[nt][0], acc[nt][1]);
        *(float2*)&Cs[(r0 + 8) * 68 + col] = make_float2(acc[nt][2], acc[nt][3]);
    }
    __syncthreads();
}

__device__ __forceinline__ void conv_epi(const float* Cs, float* gdst,
                                         const float* __restrict__ bias,
                                         float* part, int slot, int t) {
    int c = t & 63, ndt = t >> 6;
    float bb = bias[c];
    float sm = 0.f, sq = 0.f;
#pragma unroll
    for (int i = 0; i < 32; i++) {
        int pos = i * 4 + ndt;
        float v = Cs[pos * 68 + c] + bb;
        gdst[pos * 64 + c] = v;
        sm += v; sq += v * v;
    }
    atomicAdd(&part[slot * 64 + c], sm);
    atomicAdd(&part[BN_PART * 64 + slot * 64 + c], sq);
}

// bn finalize in smem: part -> sc/sh (t<64 active), caller must __syncthreads after
__device__ __forceinline__ void bn_fold(const float* part, const float* __restrict__ g,
                                        const float* __restrict__ be,
                                        float* scs, float* shs, int t) {
    if (t < 64) {
        float sm = 0.f, sq = 0.f;
#pragma unroll 8
        for (int s = 0; s < BN_PART; s++) {
            sm += part[s * 64 + t];
            sq += part[BN_PART * 64 + s * 64 + t];
        }
        float mean = sm * INV_CNT;
        float var  = sq * INV_CNT - mean * mean;
        float sc   = g[t] * rsqrtf(var + EPSV);
        scs[t] = sc;
        shs[t] = be[t] - mean * sc;
    }
}

// ---------------- conv1 (tap-mma): x -> g_ht + BN1 partials ----------------
__global__ void __launch_bounds__(256) k_conv1m(const float* __restrict__ x,
                                                const float* __restrict__ b1) {
    constexpr int LDX = 40, LDB = 104;
    extern __shared__ char dsm[];
    __half* Bs = (__half*)dsm;                     // 13312
    __half* Xs = (__half*)(dsm + 13312);           // 10880
    float*  Cs = (float*)(dsm + 13312 + 10880);    // 34816

    int bid = blockIdx.x;
    int b  = bid >> 8;
    int n0 = (bid & 255) * 4;
    int t  = threadIdx.x;

    for (int i = t; i < 64 * 48; i += 256) {
        int c = i / 48, o = i % 48;
        *(unsigned*)(Bs + c * LDB + o * 2) = *(const unsigned*)(g_W1h + c * 96 + o * 2);
    }
    if (t < 128) {
        int nd = t >> 5, r = (t >> 4) & 1, cp = t & 15;
        *(__half2*)(Xs + (nd * 34 + r * 33) * LDX + cp * 2) = __half2half2(__float2half(0.f));
    }
    {
        int i = t;
#pragma unroll
        for (int it = 0; it < 2; it++, i += 256) {
            int nd = i >> 7, cp = (i >> 3) & 15, v = i & 7;
            float4 q0 = *(const float4*)(x + (((size_t)b * CIN + 2*cp)     * NN + (n0 + nd)) * SS + v * 4);
            float4 q1 = *(const float4*)(x + (((size_t)b * CIN + 2*cp + 1) * NN + (n0 + nd)) * SS + v * 4);
            __half* dst = Xs + (nd * 34 + 1 + v * 4) * LDX + cp * 2;
            *(__half2*)(dst)           = __floats2half2_rn(q0.x, q1.x);
            *(__half2*)(dst + LDX)     = __floats2half2_rn(q0.y, q1.y);
            *(__half2*)(dst + 2 * LDX) = __floats2half2_rn(q0.z, q1.z);
            *(__half2*)(dst + 3 * LDX) = __floats2half2_rn(q0.w, q1.w);
        }
    }
    __syncthreads();
    conv_tap_mma<32, LDX, LDB>(Xs, Bs, Cs, t);
    float* gdst = g_ht + ((size_t)b * NN + n0) * SS * 64;
    conv_epi(Cs, gdst, b1, g_bn1p, bid & (BN_PART - 1), t);
}

// ---------------- hw (mma, folded BN1): relu(bn1(g_ht)) @ Wg -> g_hwh fp16 ----------
__global__ void __launch_bounds__(256) k_hwm(const float* __restrict__ g1,
                                             const float* __restrict__ be1) {
    constexpr int LD = 72;
    extern __shared__ char dsm[];
    __half* Bs = (__half*)dsm;                  // 9216
    __half* As = (__half*)(dsm + 9216);         // 18432 (union with Cs 34816)
    float*  Cs = (float*)(dsm + 9216);
    float*  scs = (float*)(dsm + 9216 + 34816);
    float*  shs = scs + 64;

    int bid = blockIdx.x;
    int b  = bid >> 8;
    int n0 = (bid & 255) * 4;
    int t  = threadIdx.x;

    bn_fold(g_bn1p, g1, be1, scs, shs, t);
    for (int i = t; i < 64 * 32; i += 256) {
        int c = i / 32, o = i % 32;
        *(unsigned*)(Bs + c * LD + o * 2) = *(const unsigned*)(g_Wgh + c * 64 + o * 2);
    }
    __syncthreads();
    const float* gsrc = g_ht + ((size_t)b * NN + n0) * SS * 64;
#pragma unroll
    for (int it = 0; it < 16; it++) {
        int i = it * 256 + t;
        int pos = i >> 5, dp = i & 31;
        float2 v = *(const float2*)(gsrc + pos * 64 + dp * 2);
        float a  = fmaxf(fmaf(v.x, scs[dp*2],   shs[dp*2]),   0.f);
        float bv = fmaxf(fmaf(v.y, scs[dp*2+1], shs[dp*2+1]), 0.f);
        *(__half2*)(As + pos * LD + dp * 2) = __floats2half2_rn(a, bv);
    }
    __syncthreads();
    {
        int wm = t >> 5, lane = t & 31;
        float acc[8][4];
#pragma unroll
        for (int nt = 0; nt < 8; nt++)
#pragma unroll
            for (int i = 0; i < 4; i++) acc[nt][i] = 0.f;
        unsigned aBase = su32(As) + ((wm * 16 + (lane & 15)) * LD + (lane >> 4) * 8) * 2;
        unsigned bBase = su32(Bs) + ((lane & 7) * LD + ((lane >> 3) & 1) * 8) * 2;
#pragma unroll
        for (int kb = 0; kb < 4; kb++) {
            unsigned a0, a1, a2, a3;
            ldmA(aBase + kb * 32, a0, a1, a2, a3);
#pragma unroll
            for (int nt = 0; nt < 8; nt++) {
                unsigned b0, b1;
                ldmB(bBase + (unsigned)(nt * 8 * LD) * 2 + kb * 32, b0, b1);
                mma16816(acc[nt], a0, a1, a2, a3, b0, b1);
            }
        }
        __syncthreads();
#pragma unroll
        for (int nt = 0; nt < 8; nt++) {
            int r0 = wm * 16 + (lane >> 2);
            int col = nt * 8 + (lane & 3) * 2;
            *(float2*)&Cs[r0 * 68 + col]       = make_float2(acc[nt][0], acc[nt][1]);
            *(float2*)&Cs[(r0 + 8) * 68 + col] = make_float2(acc[nt][2], acc[nt][3]);
        }
        __syncthreads();
    }
#pragma unroll
    for (int it = 0; it < 32; it++) {
        int idx = it * 256 + t;
        int pos = idx >> 6, d = idx & 63;
        int s = pos & 31, nd = pos >> 5;
        g_hwh[(((size_t)b * SS + s) * NN + (n0 + nd)) * CSP + d] =
            __float2half(Cs[pos * 68 + d]);
    }
}

// ---------------- GCN gather (half2, 8-unroll) + bg + BN_s partials ----------------
__global__ void __launch_bounds__(256) k_gather(const float* __restrict__ bg) {
    int bid = blockIdx.x;
    int bs  = bid >> 7;
    int n0  = (bid & 127) * 8;
    int t   = threadIdx.x;
    int wr  = t >> 5, lane = t & 31;
    int n = n0 + wr, d = lane * 2;

    const __half* hws = g_hwh + (size_t)bs * NN * CSP;
    float di = g_dinv[n];
    float sl = di * di;
    float2 f0 = __half22float2(*(const __half2*)(hws + n * 64 + d));
    float ax = f0.x * sl, ay = f0.y * sl;
    float bx = 0.f, by = 0.f;

    int jb = g_rowptr[n], je = g_rowptr[n + 1];
    int j = jb;
    for (; j + 8 <= je; j += 8) {
        int   c0 = g_col[j],   c1 = g_col[j+1], c2 = g_col[j+2], c3 = g_col[j+3];
        int   c4 = g_col[j+4], c5 = g_col[j+5], c6 = g_col[j+6], c7 = g_col[j+7];
        float w0 = g_wgt[j],   w1 = g_wgt[j+1], w2 = g_wgt[j+2], w3 = g_wgt[j+3];
        float w4 = g_wgt[j+4], w5 = g_wgt[j+5], w6 = g_wgt[j+6], w7 = g_wgt[j+7];
        float2 a0 = __half22float2(*(const __half2*)(hws + c0 * 64 + d));
        float2 a1 = __half22float2(*(const __half2*)(hws + c1 * 64 + d));
        float2 a2 = __half22float2(*(const __half2*)(hws + c2 * 64 + d));
        float2 a3 = __half22float2(*(const __half2*)(hws + c3 * 64 + d));
        float2 a4 = __half22float2(*(const __half2*)(hws + c4 * 64 + d));
        float2 a5 = __half22float2(*(const __half2*)(hws + c5 * 64 + d));
        float2 a6 = __half22float2(*(const __half2*)(hws + c6 * 64 + d));
        float2 a7 = __half22float2(*(const __half2*)(hws + c7 * 64 + d));
        ax += a0.x*w0 + a1.x*w1 + a2.x*w2 + a3.x*w3;
        ay += a0.y*w0 + a1.y*w1 + a2.y*w2 + a3.y*w3;
        bx += a4.x*w4 + a5.x*w5 + a6.x*w6 + a7.x*w7;
        by += a4.y*w4 + a5.y*w5 + a6.y*w6 + a7.y*w7;
    }
    for (; j < je; j++) {
        float w = g_wgt[j];
        float2 a = __half22float2(*(const __half2*)(hws + g_col[j] * 64 + d));
        ax += a.x * w; ay += a.y * w;
    }
    ax += bx + bg[d]; ay += by + bg[d + 1];
    *(float2*)(g_agg + ((size_t)bs * NN + n) * CSP + d) = make_float2(ax, ay);

    __shared__ float red[8 * 64];
    red[wr * 64 + d] = ax; red[wr * 64 + d + 1] = ay;
    __syncthreads();
    if (t < 64) {
        float s1 = 0.f;
#pragma unroll
        for (int r = 0; r < 8; r++) s1 += red[r * 64 + t];
        atomicAdd(&g_bnssum[bs * 64 + t], s1);
    }
    __syncthreads();
    red[wr * 64 + d] = ax * ax; red[wr * 64 + d + 1] = ay * ay;
    __syncthreads();
    if (t < 64) {
        float s2 = 0.f;
#pragma unroll
        for (int r = 0; r < 8; r++) s2 += red[r * 64 + t];
        atomicAdd(&g_bnssq[bs * 64 + t], s2);
    }
}

// ---------------- conv2 (tap-mma, folded BN_s): -> g_h2t + BN2 partials ----------
__global__ void __launch_bounds__(256) k_conv2m(const float* __restrict__ b2,
                                                const float* __restrict__ gs,
                                                const float* __restrict__ bes) {
    constexpr int LDX = 72, LDB = 200;
    extern __shared__ char dsm[];
    __half* Bs = (__half*)dsm;                     // 25600
    __half* Xs = (__half*)(dsm + 25600);           // 19584
    float*  Cs = (float*)(dsm + 25600 + 19584);    // 34816
    float*  scs = (float*)(dsm + 25600 + 19584 + 34816);  // 8192
    float*  shs = scs + 2048;                               // 8192

    int bid = blockIdx.x;
    int b  = bid >> 8;
    int n0 = (bid & 255) * 4;
    int t  = threadIdx.x;

    // folded BN_s finalize for this batch's 32 timesteps
#pragma unroll
    for (int it = 0; it < 8; it++) {
        int i = it * 256 + t;          // i = sl*64 + dch
        int sl = i >> 6, dch = i & 63;
        int bsi = b * SS + sl;
        float mean = g_bnssum[bsi * 64 + dch] * (1.f / NN);
        float var  = g_bnssq [bsi * 64 + dch] * (1.f / NN) - mean * mean;
        float sc   = gs[dch] * rsqrtf(var + EPSV);
        scs[i] = sc;
        shs[i] = bes[dch] - mean * sc;
    }
    for (int i = t; i < 64 * 96; i += 256) {
        int c = i / 96, o = i % 96;
        *(unsigned*)(Bs + c * LDB + o * 2) = *(const unsigned*)(g_W2h + c * 192 + o * 2);
    }
    if (t < 256) {
        int nd = t >> 6, r = (t >> 5) & 1, cp = t & 31;
        *(__half2*)(Xs + (nd * 34 + r * 33) * LDX + cp * 2) = __half2half2(__float2half(0.f));
    }
    __syncthreads();
#pragma unroll
    for (int it = 0; it < 16; it++) {
        int i = it * 256 + t;
        int nd = i >> 10, sidx = (i >> 5) & 31, dp = i & 31;
        int bsi = b * SS + sidx;
        float2 v  = *(const float2*)(g_agg + ((size_t)bsi * NN + (n0 + nd)) * CSP + dp * 2);
        float2 sc = *(const float2*)(scs + sidx * 64 + dp * 2);
        float2 sh = *(const float2*)(shs + sidx * 64 + dp * 2);
        float a  = fmaxf(fmaf(v.x, sc.x, sh.x), 0.f);
        float bv = fmaxf(fmaf(v.y, sc.y, sh.y), 0.f);
        *(__half2*)(Xs + (nd * 34 + 1 + sidx) * LDX + dp * 2) = __floats2half2_rn(a, bv);
    }
    __syncthreads();
    conv_tap_mma<64, LDX, LDB>(Xs, Bs, Cs, t);
    float* gdst = g_h2t + ((size_t)b * NN + n0) * SS * 64;
    conv_epi(Cs, gdst, b2, g_bn2p, bid & (BN_PART - 1), t);
}

// ---------------- output (folded BN2): relu( relu(bn2(h2)) + res ) ----------------
__global__ void __launch_bounds__(256) k_out(const float* __restrict__ x,
                                             const float* __restrict__ Wres,
                                             const float* __restrict__ bres,
                                             const float* __restrict__ g2,
                                             const float* __restrict__ be2,
                                             float* __restrict__ out) {
    extern __shared__ char dsm[];
    float* wrs = (float*)dsm;               // 2048
    float* xs  = wrs + 2048;                // 4096
    float* h2s = xs + 4096;                 // 128*68
    float* scs = h2s + 128 * 68;            // 64
    float* shs = scs + 64;                  // 64

    int bid = blockIdx.x;
    int b  = bid >> 8;
    int n0 = (bid & 255) * 4;
    int t  = threadIdx.x;

    bn_fold(g_bn2p, g2, be2, scs, shs, t);
    for (int i = t; i < 2048; i += 256) {
        int c = i >> 5, cin = i & 31;
        wrs[cin * 64 + c] = Wres[i];
    }
    for (int i = t; i < 1024; i += 256) {
        int nd = i >> 8, cin = (i >> 3) & 31, v = i & 7;
        float4 q = *(const float4*)(x + (((size_t)b * CIN + cin) * NN + (n0 + nd)) * SS + v * 4);
        *(float4*)(xs + (nd * 32 + cin) * 32 + v * 4) = q;
    }
    const float* gsrc = g_h2t + ((size_t)b * NN + n0) * SS * 64;
#pragma unroll
    for (int i = 0; i < 32; i++) {
        int idx = i * 256 + t;
        h2s[(idx >> 6) * 68 + (idx & 63)] = gsrc[idx];
    }
    __syncthreads();

    int node = t >> 6, cg = (t >> 2) & 15, sq = t & 3;
    int c0 = cg * 4, s0 = sq * 8;
    float acc[4][8];
#pragma unroll
    for (int a = 0; a < 4; a++)
#pragma unroll
        for (int i = 0; i < 8; i++) acc[a][i] = 0.f;

    const float* xbase = xs + node * 32 * 32;
    for (int cin = 0; cin < CIN; cin++) {
        float4 w4 = *(float4*)(wrs + cin * 64 + c0);
        const float* xr = xbase + cin * 32 + s0;
        float4 x0 = *(const float4*)(xr);
        float4 x1 = *(const float4*)(xr + 4);
        float xv[8] = {x0.x, x0.y, x0.z, x0.w, x1.x, x1.y, x1.z, x1.w};
        float wv[4] = {w4.x, w4.y, w4.z, w4.w};
#pragma unroll
        for (int cc = 0; cc < 4; cc++)
#pragma unroll
            for (int i = 0; i < 8; i++)
                acc[cc][i] = fmaf(wv[cc], xv[i], acc[cc][i]);
    }

    int n = n0 + node;
#pragma unroll
    for (int cc = 0; cc < 4; cc++) {
        int c = c0 + cc;
        float sc = scs[c], sh = shs[c], br = bres[c];
        float o[8];
#pragma unroll
        for (int i = 0; i < 8; i++) {
            float hraw = h2s[(node * 32 + s0 + i) * 68 + c];
            float hv = fmaxf(fmaf(hraw, sc, sh), 0.f);
            o[i] = fmaxf(hv + acc[cc][i] + br, 0.f);
        }
        float* dst = out + (((size_t)b * COUT + c) * NN + n) * SS + s0;
        *(float4*)(dst)     = make_float4(o[0], o[1], o[2], o[3]);
        *(float4*)(dst + 4) = make_float4(o[4], o[5], o[6], o[7]);
    }
}

// ---------------- launch ----------------
extern "C" void kernel_launch(void* const* d_in, const int* in_sizes, int n_in,
                              void* d_out, int out_size) {
    const float* x    = (const float*)d_in[0];
    const int*   eiw  = (const int*)d_in[1];
    const float* W1   = (const float*)d_in[2];
    const float* b1   = (const float*)d_in[3];
    const float* g1   = (const float*)d_in[4];
    const float* be1  = (const float*)d_in[5];
    const float* Wg   = (const float*)d_in[6];
    const float* bg   = (const float*)d_in[7];
    const float* gs   = (const float*)d_in[8];
    const float* bes  = (const float*)d_in[9];
    const float* W2   = (const float*)d_in[10];
    const float* b2   = (const float*)d_in[11];
    const float* g2   = (const float*)d_in[12];
    const float* be2  = (const float*)d_in[13];
    const float* Wres = (const float*)d_in[14];
    const float* bres = (const float*)d_in[15];
    float*       out  = (float*)d_out;

    const int SM_C1 = 13312 + 10880 + 34816;                     // 59008
    const int SM_C2 = 25600 + 19584 + 34816 + 16384;             // 96384
    const int SM_HW = 9216 + 34816 + 512;                        // 44544
    const int SM_OUT = (2048 + 4096 + 128 * 68 + 128) * 4;       // 59904
    cudaFuncSetAttribute(k_conv1m, cudaFuncAttributeMaxDynamicSharedMemorySize, SM_C1);
    cudaFuncSetAttribute(k_conv2m, cudaFuncAttributeMaxDynamicSharedMemorySize, SM_C2);
    cudaFuncSetAttribute(k_out,    cudaFuncAttributeMaxDynamicSharedMemorySize, SM_OUT);

    k_prep<<<48, 256>>>(eiw, W1, W2, Wg);
    k_deg <<<EE / 256, 256>>>(eiw);
    k_scan<<<1, NN>>>();
    k_fill<<<EE / 256, 256>>>(eiw);
    k_conv1m<<<B * (NN / 4), 256, SM_C1>>>(x, b1);
    k_hwm<<<B * (NN / 4), 256, SM_HW>>>(g1, be1);
    k_gather<<<B * SS * (NN / 8), 256>>>(bg);
    k_conv2m<<<B * (NN / 4), 256, SM_C2>>>(b2, gs, bes);
    k_out<<<B * (NN / 4), 256, SM_OUT>>>(x, Wres, bres, g2, be2, out);
}

// round 10
// speedup vs baseline: 2.6761x; 1.1089x over previous
#include <cuda_runtime.h>
#include <cuda_fp16.h>

// ---------------- problem constants ----------------
constexpr int B    = 4;
constexpr int CIN  = 32;
constexpr int NN   = 1024;
constexpr int SS   = 32;
constexpr int COUT = 64;
constexpr int CSP  = 64;
constexpr int EE   = 16384;
constexpr int BN_PART = 64;
constexpr float EPSV = 1e-5f;
constexpr float INV_CNT = 1.f / (float)(B * NN * SS);

// ---------------- device scratch ----------------
__device__ float  g_ht [B*NN*SS*COUT];   // conv1 raw [b][n][s][c]
__device__ __half g_hwh[B*NN*SS*CSP];    // projection [b][n][s][d] fp16 (node-major)
__device__ float  g_agg[B*NN*SS*CSP];    // gcn agg [b][n][s][d] (node-major)
__device__ float  g_h2t[B*NN*SS*COUT];   // conv2 raw [b][n][s][c]

__device__ __half g_W1h[64*96];          // [c][tap*32+cin]
__device__ __half g_W2h[64*192];         // [c][tap*64+cin]
__device__ __half g_Wgh[64*64];          // Wg^T [d][c]

__device__ int   g_is64;
__device__ int   g_deg[NN];
__device__ int   g_fill[NN];
__device__ int   g_rowptr[NN+1];
__device__ int   g_col[EE];
__device__ float g_wgt[EE];
__device__ float g_dinv[NN];

__device__ float g_bn1p[2*BN_PART*COUT];
__device__ float g_bn2p[2*BN_PART*COUT];
__device__ float g_bnssum[B*SS*CSP];
__device__ float g_bnssq [B*SS*CSP];

// ---------------- mma helpers ----------------
__device__ __forceinline__ unsigned su32(const void* p) {
    return (unsigned)__cvta_generic_to_shared(p);
}
__device__ __forceinline__ void ldmA(unsigned addr, unsigned& a0, unsigned& a1,
                                     unsigned& a2, unsigned& a3) {
    asm volatile("ldmatrix.sync.aligned.m8n8.x4.shared.b16 {%0,%1,%2,%3}, [%4];"
                 : "=r"(a0), "=r"(a1), "=r"(a2), "=r"(a3) : "r"(addr));
}
__device__ __forceinline__ void ldmB(unsigned addr, unsigned& b0, unsigned& b1) {
    asm volatile("ldmatrix.sync.aligned.m8n8.x2.shared.b16 {%0,%1}, [%2];"
                 : "=r"(b0), "=r"(b1) : "r"(addr));
}
__device__ __forceinline__ void mma16816(float* c, unsigned a0, unsigned a1,
                                         unsigned a2, unsigned a3,
                                         unsigned b0, unsigned b1) {
    asm volatile("mma.sync.aligned.m16n8k16.row.col.f32.f16.f16.f32 "
                 "{%0,%1,%2,%3},{%4,%5,%6,%7},{%8,%9},{%0,%1,%2,%3};"
                 : "+f"(c[0]), "+f"(c[1]), "+f"(c[2]), "+f"(c[3])
                 : "r"(a0), "r"(a1), "r"(a2), "r"(a3), "r"(b0), "r"(b1));
}

// ---------------- prep ----------------
__global__ void k_prep(const int* __restrict__ w, const float* __restrict__ W1,
                       const float* __restrict__ W2, const float* __restrict__ Wg) {
    int t = threadIdx.x;
    int gid = blockIdx.x * 256 + t;
    if (blockIdx.x == 0) {
        __shared__ int s_any;
        if (t == 0) s_any = 0;
        __syncthreads();
        if (w[2 * (t * 64) + 1] != 0) atomicOr(&s_any, 1);
        __syncthreads();
        if (t == 0) g_is64 = s_any ? 0 : 1;
    }
    if (gid < NN) { g_deg[gid] = 0; g_fill[gid] = 0; }
    if (gid < 2*BN_PART*COUT) { g_bn1p[gid] = 0.f; g_bn2p[gid] = 0.f; }
    if (gid < B*SS*CSP) { g_bnssum[gid] = 0.f; g_bnssq[gid] = 0.f; }
    if (gid < 64*96) {
        int c = gid / 96, r = gid % 96, tap = r >> 5, cin = r & 31;
        g_W1h[gid] = __float2half(W1[c * 96 + cin * 3 + tap]);
    }
    if (gid < 64*192) {
        int c = gid / 192, r = gid % 192, tap = r >> 6, cin = r & 63;
        g_W2h[gid] = __float2half(W2[c * 192 + cin * 3 + tap]);
    }
    if (gid < 64*64)
        g_Wgh[gid] = __float2half(Wg[(gid & 63) * 64 + (gid >> 6)]);
}

// ---------------- degree / scan / fill ----------------
__global__ void k_deg(const int* __restrict__ w) {
    int e = blockIdx.x * blockDim.x + threadIdx.x;
    if (e >= EE) return;
    int stride = g_is64 ? 2 : 1;
    int d = w[stride * (EE + e)];
    if ((unsigned)d < (unsigned)NN) atomicAdd(&g_deg[d], 1);
}
__global__ void k_scan() {
    int t = threadIdx.x, lane = t & 31, wid = t >> 5;
    int c = g_deg[t];
    g_dinv[t] = rsqrtf((float)(c + 1));
    int v = c;
#pragma unroll
    for (int o = 1; o < 32; o <<= 1) {
        int u = __shfl_up_sync(0xffffffffu, v, o);
        if (lane >= o) v += u;
    }
    __shared__ int wsum[32];
    if (lane == 31) wsum[wid] = v;
    __syncthreads();
    if (wid == 0) {
        int wv = wsum[lane];
#pragma unroll
        for (int o = 1; o < 32; o <<= 1) {
            int u = __shfl_up_sync(0xffffffffu, wv, o);
            if (lane >= o) wv += u;
        }
        wsum[lane] = wv;
    }
    __syncthreads();
    int off = (wid > 0) ? wsum[wid - 1] : 0;
    g_rowptr[t + 1] = off + v;
    if (t == 0) g_rowptr[0] = 0;
}
__global__ void k_fill(const int* __restrict__ w) {
    int e = blockIdx.x * blockDim.x + threadIdx.x;
    if (e >= EE) return;
    int stride = g_is64 ? 2 : 1;
    int s = w[stride * e];
    int d = w[stride * (EE + e)];
    if ((unsigned)s >= (unsigned)NN || (unsigned)d >= (unsigned)NN) return;
    int pos = atomicAdd(&g_fill[d], 1);
    int j = g_rowptr[d] + pos;
    g_col[j] = s;
    g_wgt[j] = g_dinv[s] * g_dinv[d];
}

// ========== tapped tensor-core conv core ==========
template<int CINT, int LDX, int LDB>
__device__ __forceinline__ void conv_tap_mma(const __half* Xs, const __half* Bs,
                                             float* Cs, int t) {
    int wm = t >> 5, lane = t & 31;
    int nd = wm >> 1;
    int sLoc = (wm & 1) * 16 + (lane & 15);
    float acc[8][4];
#pragma unroll
    for (int nt = 0; nt < 8; nt++)
#pragma unroll
        for (int i = 0; i < 4; i++) acc[nt][i] = 0.f;

    unsigned xb = su32(Xs);
    unsigned bb = su32(Bs) + ((lane & 7) * LDB + ((lane >> 3) & 1) * 8) * 2;
#pragma unroll
    for (int tap = 0; tap < 3; tap++) {
        unsigned aBase = xb + ((nd * 34 + sLoc + tap) * LDX + (lane >> 4) * 8) * 2;
#pragma unroll
        for (int kb = 0; kb < CINT / 16; kb++) {
            unsigned a0, a1, a2, a3;
            ldmA(aBase + kb * 32, a0, a1, a2, a3);
            unsigned bOff = (tap * CINT + kb * 16) * 2;
#pragma unroll
            for (int nt = 0; nt < 8; nt++) {
                unsigned b0, b1;
                ldmB(bb + (unsigned)(nt * 8 * LDB) * 2 + bOff, b0, b1);
                mma16816(acc[nt], a0, a1, a2, a3, b0, b1);
            }
        }
    }
#pragma unroll
    for (int nt = 0; nt < 8; nt++) {
        int r0 = wm * 16 + (lane >> 2);
        int col = nt * 8 + (lane & 3) * 2;
        *(float2*)&Cs[r0 * 68 + col]       = make_float2(acc[nt][0], acc[nt][1]);
        *(float2*)&Cs[(r0 + 8) * 68 + col] = make_float2(acc[nt][2], acc[nt][3]);
    }
    __syncthreads();
}

__device__ __forceinline__ void conv_epi(const float* Cs, float* gdst,
                                         const float* __restrict__ bias,
                                         float* part, int slot, int t) {
    int c = t & 63, ndt = t >> 6;
    float bb = bias[c];
    float sm = 0.f, sq = 0.f;
#pragma unroll
    for (int i = 0; i < 32; i++) {
        int pos = i * 4 + ndt;
        float v = Cs[pos * 68 + c] + bb;
        gdst[pos * 64 + c] = v;
        sm += v; sq += v * v;
    }
    atomicAdd(&part[slot * 64 + c], sm);
    atomicAdd(&part[BN_PART * 64 + slot * 64 + c], sq);
}

__device__ __forceinline__ void bn_fold(const float* part, const float* __restrict__ g,
                                        const float* __restrict__ be,
                                        float* scs, float* shs, int t) {
    if (t < 64) {
        float sm = 0.f, sq = 0.f;
#pragma unroll 8
        for (int s = 0; s < BN_PART; s++) {
            sm += part[s * 64 + t];
            sq += part[BN_PART * 64 + s * 64 + t];
        }
        float mean = sm * INV_CNT;
        float var  = sq * INV_CNT - mean * mean;
        float sc   = g[t] * rsqrtf(var + EPSV);
        scs[t] = sc;
        shs[t] = be[t] - mean * sc;
    }
}

// ---------------- conv1 (tap-mma): x -> g_ht + BN1 partials ----------------
__global__ void __launch_bounds__(256) k_conv1m(const float* __restrict__ x,
                                                const float* __restrict__ b1) {
    constexpr int LDX = 40, LDB = 104;
    extern __shared__ char dsm[];
    __half* Bs = (__half*)dsm;                     // 13312
    __half* Xs = (__half*)(dsm + 13312);           // 10880
    float*  Cs = (float*)(dsm + 13312 + 10880);    // 34816

    int bid = blockIdx.x;
    int b  = bid >> 8;
    int n0 = (bid & 255) * 4;
    int t  = threadIdx.x;

    for (int i = t; i < 64 * 48; i += 256) {
        int c = i / 48, o = i % 48;
        *(unsigned*)(Bs + c * LDB + o * 2) = *(const unsigned*)(g_W1h + c * 96 + o * 2);
    }
    if (t < 128) {
        int nd = t >> 5, r = (t >> 4) & 1, cp = t & 15;
        *(__half2*)(Xs + (nd * 34 + r * 33) * LDX + cp * 2) = __half2half2(__float2half(0.f));
    }
    {
        int i = t;
#pragma unroll
        for (int it = 0; it < 2; it++, i += 256) {
            int nd = i >> 7, cp = (i >> 3) & 15, v = i & 7;
            float4 q0 = *(const float4*)(x + (((size_t)b * CIN + 2*cp)     * NN + (n0 + nd)) * SS + v * 4);
            float4 q1 = *(const float4*)(x + (((size_t)b * CIN + 2*cp + 1) * NN + (n0 + nd)) * SS + v * 4);
            __half* dst = Xs + (nd * 34 + 1 + v * 4) * LDX + cp * 2;
            *(__half2*)(dst)           = __floats2half2_rn(q0.x, q1.x);
            *(__half2*)(dst + LDX)     = __floats2half2_rn(q0.y, q1.y);
            *(__half2*)(dst + 2 * LDX) = __floats2half2_rn(q0.z, q1.z);
            *(__half2*)(dst + 3 * LDX) = __floats2half2_rn(q0.w, q1.w);
        }
    }
    __syncthreads();
    conv_tap_mma<32, LDX, LDB>(Xs, Bs, Cs, t);
    float* gdst = g_ht + ((size_t)b * NN + n0) * SS * 64;
    conv_epi(Cs, gdst, b1, g_bn1p, bid & (BN_PART - 1), t);
}

// ---------------- hw (mma, folded BN1): relu(bn1(g_ht)) @ Wg -> g_hwh node-major ------
__global__ void __launch_bounds__(256) k_hwm(const float* __restrict__ g1,
                                             const float* __restrict__ be1) {
    constexpr int LD = 72;
    extern __shared__ char dsm[];
    __half* Bs = (__half*)dsm;                  // 9216
    __half* As = (__half*)(dsm + 9216);         // 18432 (union with Cs 34816)
    float*  Cs = (float*)(dsm + 9216);
    float*  scs = (float*)(dsm + 9216 + 34816);
    float*  shs = scs + 64;

    int bid = blockIdx.x;
    int b  = bid >> 8;
    int n0 = (bid & 255) * 4;
    int t  = threadIdx.x;

    bn_fold(g_bn1p, g1, be1, scs, shs, t);
    for (int i = t; i < 64 * 32; i += 256) {
        int c = i / 32, o = i % 32;
        *(unsigned*)(Bs + c * LD + o * 2) = *(const unsigned*)(g_Wgh + c * 64 + o * 2);
    }
    __syncthreads();
    const float* gsrc = g_ht + ((size_t)b * NN + n0) * SS * 64;
#pragma unroll
    for (int it = 0; it < 16; it++) {
        int i = it * 256 + t;
        int pos = i >> 5, dp = i & 31;
        float2 v = *(const float2*)(gsrc + pos * 64 + dp * 2);
        float a  = fmaxf(fmaf(v.x, scs[dp*2],   shs[dp*2]),   0.f);
        float bv = fmaxf(fmaf(v.y, scs[dp*2+1], shs[dp*2+1]), 0.f);
        *(__half2*)(As + pos * LD + dp * 2) = __floats2half2_rn(a, bv);
    }
    __syncthreads();
    {
        int wm = t >> 5, lane = t & 31;
        float acc[8][4];
#pragma unroll
        for (int nt = 0; nt < 8; nt++)
#pragma unroll
            for (int i = 0; i < 4; i++) acc[nt][i] = 0.f;
        unsigned aBase = su32(As) + ((wm * 16 + (lane & 15)) * LD + (lane >> 4) * 8) * 2;
        unsigned bBase = su32(Bs) + ((lane & 7) * LD + ((lane >> 3) & 1) * 8) * 2;
#pragma unroll
        for (int kb = 0; kb < 4; kb++) {
            unsigned a0, a1, a2, a3;
            ldmA(aBase + kb * 32, a0, a1, a2, a3);
#pragma unroll
            for (int nt = 0; nt < 8; nt++) {
                unsigned b0, b1;
                ldmB(bBase + (unsigned)(nt * 8 * LD) * 2 + kb * 32, b0, b1);
                mma16816(acc[nt], a0, a1, a2, a3, b0, b1);
            }
        }
        __syncthreads();
#pragma unroll
        for (int nt = 0; nt < 8; nt++) {
            int r0 = wm * 16 + (lane >> 2);
            int col = nt * 8 + (lane & 3) * 2;
            *(float2*)&Cs[r0 * 68 + col]       = make_float2(acc[nt][0], acc[nt][1]);
            *(float2*)&Cs[(r0 + 8) * 68 + col] = make_float2(acc[nt][2], acc[nt][3]);
        }
        __syncthreads();
    }
    __half* gdst = g_hwh + ((size_t)b * NN + n0) * SS * 64;
#pragma unroll
    for (int it = 0; it < 16; it++) {
        int i = it * 256 + t;
        int pos = i >> 5, dp = i & 31;
        float2 f = *(const float2*)&Cs[pos * 68 + dp * 2];
        *(__half2*)(gdst + pos * 64 + dp * 2) = __floats2half2_rn(f.x, f.y);
    }
}

// ---------------- GCN gather: block = (b,n), all 32 timesteps per edge ----------------
__device__ __forceinline__ void acc8(float* acc, uint4 q, float w) {
    __half2* hp = (__half2*)&q;
#pragma unroll
    for (int k = 0; k < 4; k++) {
        float2 f = __half22float2(hp[k]);
        acc[2*k]   = fmaf(f.x, w, acc[2*k]);
        acc[2*k+1] = fmaf(f.y, w, acc[2*k+1]);
    }
}
__global__ void __launch_bounds__(256) k_gather(const float* __restrict__ bg) {
    int bid = blockIdx.x;                 // b*NN + n
    int b = bid >> 10, n = bid & 1023;
    int t = threadIdx.x;
    int o = t * 8;                        // halves offset within 2048-row

    const __half* base = g_hwh + (size_t)b * NN * 2048;
    float di = g_dinv[n];
    float sl = di * di;
    float acc[8];
#pragma unroll
    for (int k = 0; k < 8; k++) acc[k] = 0.f;
    {
        uint4 q = *(const uint4*)(base + (size_t)n * 2048 + o);
        acc8(acc, q, sl);                 // self loop
    }
    int jb = g_rowptr[n], je = g_rowptr[n + 1];
    int j = jb;
    for (; j + 4 <= je; j += 4) {
        int   c0 = g_col[j],   c1 = g_col[j+1], c2 = g_col[j+2], c3 = g_col[j+3];
        float w0 = g_wgt[j],   w1 = g_wgt[j+1], w2 = g_wgt[j+2], w3 = g_wgt[j+3];
        uint4 q0 = *(const uint4*)(base + (size_t)c0 * 2048 + o);
        uint4 q1 = *(const uint4*)(base + (size_t)c1 * 2048 + o);
        uint4 q2 = *(const uint4*)(base + (size_t)c2 * 2048 + o);
        uint4 q3 = *(const uint4*)(base + (size_t)c3 * 2048 + o);
        acc8(acc, q0, w0); acc8(acc, q1, w1); acc8(acc, q2, w2); acc8(acc, q3, w3);
    }
    for (; j < je; j++) {
        uint4 q = *(const uint4*)(base + (size_t)g_col[j] * 2048 + o);
        acc8(acc, q, g_wgt[j]);
    }
    int dbase = o & 63;
#pragma unroll
    for (int k = 0; k < 8; k++) acc[k] += bg[dbase + k];
    float4* dst = (float4*)(g_agg + (size_t)bid * 2048 + o);
    dst[0] = make_float4(acc[0], acc[1], acc[2], acc[3]);
    dst[1] = make_float4(acc[4], acc[5], acc[6], acc[7]);
}

// ---------------- BN_s stats over nodes: g_agg [b][n][s][d] -> g_bnssum/ssq ------------
__global__ void __launch_bounds__(256) k_stats() {
    int bid = blockIdx.x;                 // b(4) x s(32) x q(4)
    int b = bid >> 7, s = (bid >> 2) & 31, q = bid & 3;
    int t = threadIdx.x;
    int d = t & 63, ng = t >> 6;          // 4 node lanes
    float sm = 0.f, sq = 0.f;
    const float* base = g_agg + ((size_t)b * NN + q * 256) * 2048 + s * 64 + d;
#pragma unroll 8
    for (int i = 0; i < 64; i++) {
        float v = base[(size_t)(i * 4 + ng) * 2048];
        sm += v; sq += v * v;
    }
    __shared__ float r1[256], r2[256];
    r1[t] = sm; r2[t] = sq;
    __syncthreads();
    if (t < 64) {
        float s1 = r1[t] + r1[t+64] + r1[t+128] + r1[t+192];
        float s2 = r2[t] + r2[t+64] + r2[t+128] + r2[t+192];
        atomicAdd(&g_bnssum[(b * SS + s) * 64 + t], s1);
        atomicAdd(&g_bnssq [(b * SS + s) * 64 + t], s2);
    }
}

// ---------------- conv2 (tap-mma, folded BN_s): -> g_h2t + BN2 partials ----------
__global__ void __launch_bounds__(256) k_conv2m(const float* __restrict__ b2,
                                                const float* __restrict__ gs,
                                                const float* __restrict__ bes) {
    constexpr int LDX = 72, LDB = 200;
    extern __shared__ char dsm[];
    __half* Bs = (__half*)dsm;                     // 25600
    __half* Xs = (__half*)(dsm + 25600);           // 19584
    float*  Cs = (float*)(dsm + 25600 + 19584);    // 34816
    float*  scs = (float*)(dsm + 25600 + 19584 + 34816);  // 8192
    float*  shs = scs + 2048;                               // 8192

    int bid = blockIdx.x;
    int b  = bid >> 8;
    int n0 = (bid & 255) * 4;
    int t  = threadIdx.x;

#pragma unroll
    for (int it = 0; it < 8; it++) {
        int i = it * 256 + t;          // sl*64 + dch
        int sl = i >> 6, dch = i & 63;
        int bsi = b * SS + sl;
        float mean = g_bnssum[bsi * 64 + dch] * (1.f / NN);
        float var  = g_bnssq [bsi * 64 + dch] * (1.f / NN) - mean * mean;
        float sc   = gs[dch] * rsqrtf(var + EPSV);
        scs[i] = sc;
        shs[i] = bes[dch] - mean * sc;
    }
    for (int i = t; i < 64 * 96; i += 256) {
        int c = i / 96, o = i % 96;
        *(unsigned*)(Bs + c * LDB + o * 2) = *(const unsigned*)(g_W2h + c * 192 + o * 2);
    }
    if (t < 256) {
        int nd = t >> 6, r = (t >> 5) & 1, cp = t & 31;
        *(__half2*)(Xs + (nd * 34 + r * 33) * LDX + cp * 2) = __half2half2(__float2half(0.f));
    }
    __syncthreads();
    const float* asrc = g_agg + ((size_t)b * NN + n0) * 2048;
#pragma unroll
    for (int it = 0; it < 16; it++) {
        int i = it * 256 + t;
        int nd = i >> 10, sidx = (i >> 5) & 31, dp = i & 31;
        float2 v  = *(const float2*)(asrc + (size_t)(nd * 32 + sidx) * 64 + dp * 2);
        float2 sc = *(const float2*)(scs + sidx * 64 + dp * 2);
        float2 sh = *(const float2*)(shs + sidx * 64 + dp * 2);
        float a  = fmaxf(fmaf(v.x, sc.x, sh.x), 0.f);
        float bv = fmaxf(fmaf(v.y, sc.y, sh.y), 0.f);
        *(__half2*)(Xs + (nd * 34 + 1 + sidx) * LDX + dp * 2) = __floats2half2_rn(a, bv);
    }
    __syncthreads();
    conv_tap_mma<64, LDX, LDB>(Xs, Bs, Cs, t);
    float* gdst = g_h2t + ((size_t)b * NN + n0) * SS * 64;
    conv_epi(Cs, gdst, b2, g_bn2p, bid & (BN_PART - 1), t);
}

// ---------------- output (folded BN2): relu( relu(bn2(h2)) + res ) ----------------
__global__ void __launch_bounds__(256) k_out(const float* __restrict__ x,
                                             const float* __restrict__ Wres,
                                             const float* __restrict__ bres,
                                             const float* __restrict__ g2,
                                             const float* __restrict__ be2,
                                             float* __restrict__ out) {
    extern __shared__ char dsm[];
    float* wrs = (float*)dsm;               // 2048
    float* xs  = wrs + 2048;                // 4096
    float* h2s = xs + 4096;                 // 128*68
    float* scs = h2s + 128 * 68;            // 64
    float* shs = scs + 64;                  // 64

    int bid = blockIdx.x;
    int b  = bid >> 8;
    int n0 = (bid & 255) * 4;
    int t  = threadIdx.x;

    bn_fold(g_bn2p, g2, be2, scs, shs, t);
    for (int i = t; i < 2048; i += 256) {
        int c = i >> 5, cin = i & 31;
        wrs[cin * 64 + c] = Wres[i];
    }
    for (int i = t; i < 1024; i += 256) {
        int nd = i >> 8, cin = (i >> 3) & 31, v = i & 7;
        float4 q = *(const float4*)(x + (((size_t)b * CIN + cin) * NN + (n0 + nd)) * SS + v * 4);
        *(float4*)(xs + (nd * 32 + cin) * 32 + v * 4) = q;
    }
    const float* gsrc = g_h2t + ((size_t)b * NN + n0) * SS * 64;
#pragma unroll
    for (int i = 0; i < 32; i++) {
        int idx = i * 256 + t;
        h2s[(idx >> 6) * 68 + (idx & 63)] = gsrc[idx];
    }
    __syncthreads();

    int node = t >> 6, cg = (t >> 2) & 15, sq = t & 3;
    int c0 = cg * 4, s0 = sq * 8;
    float acc[4][8];
#pragma unroll
    for (int a = 0; a < 4; a++)
#pragma unroll
        for (int i = 0; i < 8; i++) acc[a][i] = 0.f;

    const float* xbase = xs + node * 32 * 32;
    for (int cin = 0; cin < CIN; cin++) {
        float4 w4 = *(float4*)(wrs + cin * 64 + c0);
        const float* xr = xbase + cin * 32 + s0;
        float4 x0 = *(const float4*)(xr);
        float4 x1 = *(const float4*)(xr + 4);
        float xv[8] = {x0.x, x0.y, x0.z, x0.w, x1.x, x1.y, x1.z, x1.w};
        float wv[4] = {w4.x, w4.y, w4.z, w4.w};
#pragma unroll
        for (int cc = 0; cc < 4; cc++)
#pragma unroll
            for (int i = 0; i < 8; i++)
                acc[cc][i] = fmaf(wv[cc], xv[i], acc[cc][i]);
    }

    int n = n0 + node;
#pragma unroll
    for (int cc = 0; cc < 4; cc++) {
        int c = c0 + cc;
        float sc = scs[c], sh = shs[c], br = bres[c];
        float o[8];
#pragma unroll
        for (int i = 0; i < 8; i++) {
            float hraw = h2s[(node * 32 + s0 + i) * 68 + c];
            float hv = fmaxf(fmaf(hraw, sc, sh), 0.f);
            o[i] = fmaxf(hv + acc[cc][i] + br, 0.f);
        }
        float* dst = out + (((size_t)b * COUT + c) * NN + n) * SS + s0;
        *(float4*)(dst)     = make_float4(o[0], o[1], o[2], o[3]);
        *(float4*)(dst + 4) = make_float4(o[4], o[5], o[6], o[7]);
    }
}

// ---------------- launch (linear, single stream) ----------------
extern "C" void kernel_launch(void* const* d_in, const int* in_sizes, int n_in,
                              void* d_out, int out_size) {
    const float* x    = (const float*)d_in[0];
    const int*   eiw  = (const int*)d_in[1];
    const float* W1   = (const float*)d_in[2];
    const float* b1   = (const float*)d_in[3];
    const float* g1   = (const float*)d_in[4];
    const float* be1  = (const float*)d_in[5];
    const float* Wg   = (const float*)d_in[6];
    const float* bg   = (const float*)d_in[7];
    const float* gs   = (const float*)d_in[8];
    const float* bes  = (const float*)d_in[9];
    const float* W2   = (const float*)d_in[10];
    const float* b2   = (const float*)d_in[11];
    const float* g2   = (const float*)d_in[12];
    const float* be2  = (const float*)d_in[13];
    const float* Wres = (const float*)d_in[14];
    const float* bres = (const float*)d_in[15];
    float*       out  = (float*)d_out;

    const int SM_C1 = 13312 + 10880 + 34816;                     // 59008
    const int SM_C2 = 25600 + 19584 + 34816 + 16384;             // 96384
    const int SM_HW = 9216 + 34816 + 512;                        // 44544
    const int SM_OUT = (2048 + 4096 + 128 * 68 + 128) * 4;       // 59904
    cudaFuncSetAttribute(k_conv1m, cudaFuncAttributeMaxDynamicSharedMemorySize, SM_C1);
    cudaFuncSetAttribute(k_conv2m, cudaFuncAttributeMaxDynamicSharedMemorySize, SM_C2);
    cudaFuncSetAttribute(k_out,    cudaFuncAttributeMaxDynamicSharedMemorySize, SM_OUT);

    k_prep<<<48, 256>>>(eiw, W1, W2, Wg);
    k_deg <<<EE / 256, 256>>>(eiw);
    k_scan<<<1, NN>>>();
    k_fill<<<EE / 256, 256>>>(eiw);
    k_conv1m<<<B * (NN / 4), 256, SM_C1>>>(x, b1);
    k_hwm<<<B * (NN / 4), 256, SM_HW>>>(g1, be1);
    k_gather<<<B * NN, 256>>>(bg);
    k_stats<<<B * SS * 4, 256>>>();
    k_conv2m<<<B * (NN / 4), 256, SM_C2>>>(b2, gs, bes);
    k_out<<<B * (NN / 4), 256, SM_OUT>>>(x, Wres, bres, g2, be2, out);
}